// round 14
// baseline (speedup 1.0000x reference)
#include <cuda_runtime.h>
#include <cuda_fp16.h>
#include <cstdint>

typedef unsigned long long u64;
typedef unsigned int u32;

#define DIMC    128
#define KC      1024
#define SDIM    256
#define XD      8
#define BTOT    262144

#define VROWS   64
#define VTHR    256
#define NCHUNK  8
#define CHN     128
#define CAND_MAX 32
#define APW     68
#define DOTSCALE 0.0009765625f   // 2^-10 exact
#define CHBYTES 34816
#define REPAIR_GAP 2.0e-5f

#define DROWS   128
#define DTHR    512

// ---------------- scratch globals ----------------
__device__ float   g_cnorm[KC];
__device__ __half  g_ch16[KC * DIMC];
__device__ float   g_ze[(size_t)BTOT * DIMC];
__device__ float   g_znorm[BTOT];
__device__ float   g_zabs[BTOT];
__device__ int     g_idx[BTOT];
__device__ __half  g_w1h[128 * 384];
__device__ __half  g_w1l[128 * 384];
__device__ __half  g_w2h[128 * 128];
__device__ __half  g_w2l[128 * 128];
__device__ __half  g_e1h[128 * 272];
__device__ __half  g_e1l[128 * 272];
__device__ __half  g_e2h[128 * 128];
__device__ __half  g_e2l[128 * 128];
__device__ int     g_rcnt;
__device__ int     g_rlist[BTOT];

// ---------------- prep ----------------
__global__ void vq_prep(const float* __restrict__ cb) {
    int j = blockIdx.x;
    int d = threadIdx.x;
    float v = cb[j * DIMC + d];
    g_ch16[j * DIMC + d] = __float2half_rn(v * 1024.0f);
    __shared__ float red[DIMC];
    red[d] = v * v;
    __syncthreads();
    #pragma unroll
    for (int s = 64; s > 0; s >>= 1) {
        if (d < s) red[d] += red[d + s];
        __syncthreads();
    }
    if (d == 0) g_cnorm[j] = red[0];
}

__global__ void dec_prep(const float* __restrict__ dw1, const float* __restrict__ dw2) {
    int i = blockIdx.x * 256 + threadIdx.x;
    if (i < 128 * 384) {
        int n = i / 384, k = i % 384;
        float v = dw1[k * 128 + n] * 64.0f;
        __half h = __float2half_rn(v);
        g_w1h[i] = h;
        g_w1l[i] = __float2half_rn(v - __half2float(h));
    } else if (i < 128 * 384 + 128 * 128) {
        int j = i - 128 * 384;
        int n = j / 128, k = j % 128;
        float v = dw2[k * 128 + n] * 64.0f;
        __half h = __float2half_rn(v);
        g_w2h[j] = h;
        g_w2l[j] = __float2half_rn(v - __half2float(h));
    }
}

__global__ void enc_prep(const float* __restrict__ ew1, const float* __restrict__ ew2) {
    int i = blockIdx.x * 256 + threadIdx.x;
    if (i == 0) g_rcnt = 0;
    if (i < 128 * 272) {
        int n = i / 272, k = i % 272;
        float v = (k < 264) ? ew1[(size_t)k * 128 + n] * 64.0f : 0.0f;
        __half h = __float2half_rn(v);
        g_e1h[i] = h;
        g_e1l[i] = __float2half_rn(v - __half2float(h));
    } else if (i < 128 * 272 + 128 * 128) {
        int j = i - 128 * 272;
        int n = j / 128, k = j % 128;
        float v = ew2[k * 128 + n] * 64.0f;
        __half h = __float2half_rn(v);
        g_e2h[j] = h;
        g_e2l[j] = __float2half_rn(v - __half2float(h));
    }
}

// ---------------- packed f32x2 helpers ----------------
__device__ __forceinline__ u64 dup2(float w) {
    u64 r; unsigned u = __float_as_uint(w);
    asm("mov.b64 %0, {%1, %1};" : "=l"(r) : "r"(u));
    return r;
}
__device__ __forceinline__ void ffma2(u64& d, u64 a, u64 b) {
    asm("fma.rn.f32x2 %0, %1, %2, %0;" : "+l"(d) : "l"(a), "l"(b));
}
__device__ __forceinline__ float2 unpk(u64 v) {
    unsigned lo, hi;
    asm("mov.b64 {%0, %1}, %2;" : "=r"(lo), "=r"(hi) : "l"(v));
    return make_float2(__uint_as_float(lo), __uint_as_float(hi));
}

// ---------------- fp16 mma + cp.async helpers ----------------
__device__ __forceinline__ void mma16816(float* d, u32 a0, u32 a1, u32 a2, u32 a3,
                                         u32 b0, u32 b1) {
    asm volatile(
        "mma.sync.aligned.m16n8k16.row.col.f32.f16.f16.f32 "
        "{%0,%1,%2,%3}, {%4,%5,%6,%7}, {%8,%9}, {%0,%1,%2,%3};"
        : "+f"(d[0]), "+f"(d[1]), "+f"(d[2]), "+f"(d[3])
        : "r"(a0), "r"(a1), "r"(a2), "r"(a3), "r"(b0), "r"(b1));
}
__device__ __forceinline__ u32 smem_u32(const void* p) {
    u32 a;
    asm("{ .reg .u64 t; cvta.to.shared.u64 t, %1; cvt.u32.u64 %0, t; }" : "=r"(a) : "l"(p));
    return a;
}
__device__ __forceinline__ void cp16(u32 dst, const void* src) {
    asm volatile("cp.async.cg.shared.global [%0], [%1], 16;" :: "r"(dst), "l"(src) : "memory");
}
#define CP_COMMIT() asm volatile("cp.async.commit_group;" ::: "memory")
#define CP_WAIT0()  asm volatile("cp.async.wait_group 0;" ::: "memory")

__device__ __forceinline__ u32 fmap(float f) {
    u32 u = __float_as_uint(f);
    return (u & 0x80000000u) ? ~u : (u | 0x80000000u);
}
__device__ __forceinline__ float finv(u32 m) {
    u32 u = (m & 0x80000000u) ? (m ^ 0x80000000u) : ~m;
    return __uint_as_float(u);
}

// ---------------- encoder: L1+L2 fp16 4-term, L3 exact fp32 (R13) -----------
#define ENC_SMEM 139264
#define EROWS   128
#define ETHR    512

__global__ void __launch_bounds__(ETHR, 1) enc_kernel(
    const float* __restrict__ state, const float* __restrict__ x,
    const float* __restrict__ eb1, const float* __restrict__ eb2,
    const float* __restrict__ ew3, const float* __restrict__ eb3,
    float* __restrict__ out, int nrows)
{
    extern __shared__ char smc[];
    u32* xhS = (u32*)(smc);
    u32* xlS = (u32*)(smc + 34816);
    u32* whS = (u32*)(smc + 69632);
    u32* wlS = (u32*)(smc + 104448);
    float* h2S = (float*)(smc + 69632);
    float* zeS = (float*)(smc);

    const int tid  = threadIdx.x;
    const int wid  = tid >> 5, lane = tid & 31;
    const int g    = lane >> 2, tg = lane & 3;
    const int rbase = blockIdx.x * EROWS;

    const int mbase = (wid >> 2) * 32;
    const int nq    = (wid & 3) * 32;

    float dacc[2][4][4];
    #pragma unroll
    for (int mt = 0; mt < 2; mt++)
        #pragma unroll
        for (int nt = 0; nt < 4; nt++) {
            dacc[mt][nt][0] = 0.f; dacc[mt][nt][1] = 0.f;
            dacc[mt][nt][2] = 0.f; dacc[mt][nt][3] = 0.f;
        }

    for (int ch = 0; ch < 3; ch++) {
        const int kwords = (ch < 2) ? 64 : 8;
        if (ch < 2) {
            for (int i = tid; i < EROWS * 64; i += ETHR) {
                int r = i >> 6, cw = i & 63;
                float2 v = *(const float2*)(state + (size_t)(rbase + r) * SDIM + ch * 128 + 2 * cw);
                float v0 = v.x * 16.0f, v1 = v.y * 16.0f;
                __half h0 = __float2half_rn(v0), h1 = __float2half_rn(v1);
                __half l0 = __float2half_rn(v0 - __half2float(h0));
                __half l1 = __float2half_rn(v1 - __half2float(h1));
                __half2 hp(h0, h1), lp(l0, l1);
                xhS[r * APW + cw] = *(u32*)&hp;
                xlS[r * APW + cw] = *(u32*)&lp;
            }
        } else {
            for (int i = tid; i < EROWS * 8; i += ETHR) {
                int r = i >> 3, cw = i & 7;
                u32 hw = 0, lw = 0;
                if (cw < 4) {
                    float2 v = *(const float2*)(x + (size_t)(rbase + r) * XD + 2 * cw);
                    float v0 = v.x * 16.0f, v1 = v.y * 16.0f;
                    __half h0 = __float2half_rn(v0), h1 = __float2half_rn(v1);
                    __half l0 = __float2half_rn(v0 - __half2float(h0));
                    __half l1 = __float2half_rn(v1 - __half2float(h1));
                    __half2 hp(h0, h1), lp(l0, l1);
                    hw = *(u32*)&hp; lw = *(u32*)&lp;
                }
                xhS[r * APW + cw] = hw;
                xlS[r * APW + cw] = lw;
            }
        }
        {
            const u32* srcH = (const u32*)g_e1h;
            const u32* srcL = (const u32*)g_e1l;
            for (int i = tid; i < 128 * kwords; i += ETHR) {
                int n = i / kwords, cw = i % kwords;
                int woff = n * 136 + ch * 64 + cw;
                whS[n * APW + cw] = srcH[woff];
                wlS[n * APW + cw] = srcL[woff];
            }
        }
        __syncthreads();

        const int ktmax = (ch < 2) ? 8 : 1;
        for (int kt = 0; kt < ktmax; kt++) {
            const int ka = kt * 8 + tg;
            u32 ah[2][4], al[2][4];
            #pragma unroll
            for (int mt = 0; mt < 2; mt++) {
                const int rb = (mbase + mt * 16 + g) * APW;
                ah[mt][0] = xhS[rb + ka];
                ah[mt][1] = xhS[rb + 8 * APW + ka];
                ah[mt][2] = xhS[rb + ka + 4];
                ah[mt][3] = xhS[rb + 8 * APW + ka + 4];
                al[mt][0] = xlS[rb + ka];
                al[mt][1] = xlS[rb + 8 * APW + ka];
                al[mt][2] = xlS[rb + ka + 4];
                al[mt][3] = xlS[rb + 8 * APW + ka + 4];
            }
            #pragma unroll
            for (int nt = 0; nt < 4; nt++) {
                const int w = (nq + nt * 8 + g) * APW + ka;
                const u32 bh0 = whS[w], bh1 = whS[w + 4];
                const u32 bl0 = wlS[w], bl1 = wlS[w + 4];
                #pragma unroll
                for (int mt = 0; mt < 2; mt++) {
                    mma16816(dacc[mt][nt], ah[mt][0], ah[mt][1], ah[mt][2], ah[mt][3], bh0, bh1);
                    mma16816(dacc[mt][nt], al[mt][0], al[mt][1], al[mt][2], al[mt][3], bh0, bh1);
                    mma16816(dacc[mt][nt], ah[mt][0], ah[mt][1], ah[mt][2], ah[mt][3], bl0, bl1);
                    mma16816(dacc[mt][nt], al[mt][0], al[mt][1], al[mt][2], al[mt][3], bl0, bl1);
                }
            }
        }
        __syncthreads();
    }

    #pragma unroll
    for (int mt = 0; mt < 2; mt++) {
        const int rA = mbase + mt * 16 + g, rB = rA + 8;
        #pragma unroll
        for (int nt = 0; nt < 4; nt++) {
            const int jb = nq + nt * 8 + 2 * tg;
            const float b0v = __ldg(eb1 + jb), b1v = __ldg(eb1 + jb + 1);
            float* d = dacc[mt][nt];
            float s0 = fmaxf(fmaf(d[0], DOTSCALE, b0v), 0.f) * 16.0f;
            float s1 = fmaxf(fmaf(d[1], DOTSCALE, b1v), 0.f) * 16.0f;
            float s2 = fmaxf(fmaf(d[2], DOTSCALE, b0v), 0.f) * 16.0f;
            float s3 = fmaxf(fmaf(d[3], DOTSCALE, b1v), 0.f) * 16.0f;
            const int w = (nq >> 1) + nt * 4 + tg;
            __half h0 = __float2half_rn(s0), h1 = __float2half_rn(s1);
            __half l0 = __float2half_rn(s0 - __half2float(h0));
            __half l1 = __float2half_rn(s1 - __half2float(h1));
            __half2 hpA(h0, h1), lpA(l0, l1);
            xhS[rA * APW + w] = *(u32*)&hpA;
            xlS[rA * APW + w] = *(u32*)&lpA;
            __half h2 = __float2half_rn(s2), h3 = __float2half_rn(s3);
            __half l2 = __float2half_rn(s2 - __half2float(h2));
            __half l3 = __float2half_rn(s3 - __half2float(h3));
            __half2 hpB(h2, h3), lpB(l2, l3);
            xhS[rB * APW + w] = *(u32*)&hpB;
            xlS[rB * APW + w] = *(u32*)&lpB;
        }
    }
    {
        const u32* srcH = (const u32*)g_e2h;
        const u32* srcL = (const u32*)g_e2l;
        for (int i = tid; i < 128 * 64; i += ETHR) {
            int n = i >> 6, cw = i & 63;
            whS[n * APW + cw] = srcH[n * 64 + cw];
            wlS[n * APW + cw] = srcL[n * 64 + cw];
        }
    }
    __syncthreads();

    #pragma unroll
    for (int mt = 0; mt < 2; mt++)
        #pragma unroll
        for (int nt = 0; nt < 4; nt++) {
            dacc[mt][nt][0] = 0.f; dacc[mt][nt][1] = 0.f;
            dacc[mt][nt][2] = 0.f; dacc[mt][nt][3] = 0.f;
        }
    #pragma unroll
    for (int kt = 0; kt < 8; kt++) {
        const int ka = kt * 8 + tg;
        u32 ah[2][4], al[2][4];
        #pragma unroll
        for (int mt = 0; mt < 2; mt++) {
            const int rb = (mbase + mt * 16 + g) * APW;
            ah[mt][0] = xhS[rb + ka];
            ah[mt][1] = xhS[rb + 8 * APW + ka];
            ah[mt][2] = xhS[rb + ka + 4];
            ah[mt][3] = xhS[rb + 8 * APW + ka + 4];
            al[mt][0] = xlS[rb + ka];
            al[mt][1] = xlS[rb + 8 * APW + ka];
            al[mt][2] = xlS[rb + ka + 4];
            al[mt][3] = xlS[rb + 8 * APW + ka + 4];
        }
        #pragma unroll
        for (int nt = 0; nt < 4; nt++) {
            const int w = (nq + nt * 8 + g) * APW + ka;
            const u32 bh0 = whS[w], bh1 = whS[w + 4];
            const u32 bl0 = wlS[w], bl1 = wlS[w + 4];
            #pragma unroll
            for (int mt = 0; mt < 2; mt++) {
                mma16816(dacc[mt][nt], ah[mt][0], ah[mt][1], ah[mt][2], ah[mt][3], bh0, bh1);
                mma16816(dacc[mt][nt], al[mt][0], al[mt][1], al[mt][2], al[mt][3], bh0, bh1);
                mma16816(dacc[mt][nt], ah[mt][0], ah[mt][1], ah[mt][2], ah[mt][3], bl0, bl1);
                mma16816(dacc[mt][nt], al[mt][0], al[mt][1], al[mt][2], al[mt][3], bl0, bl1);
            }
        }
    }
    __syncthreads();

    #pragma unroll
    for (int mt = 0; mt < 2; mt++) {
        const int rA = mbase + mt * 16 + g, rB = rA + 8;
        #pragma unroll
        for (int nt = 0; nt < 4; nt++) {
            const int jb = nq + nt * 8 + 2 * tg;
            const float b0v = __ldg(eb2 + jb), b1v = __ldg(eb2 + jb + 1);
            float* d = dacc[mt][nt];
            h2S[jb * 132 + rA]       = fmaxf(fmaf(d[0], DOTSCALE, b0v), 0.f);
            h2S[(jb + 1) * 132 + rA] = fmaxf(fmaf(d[1], DOTSCALE, b1v), 0.f);
            h2S[jb * 132 + rB]       = fmaxf(fmaf(d[2], DOTSCALE, b0v), 0.f);
            h2S[(jb + 1) * 132 + rB] = fmaxf(fmaf(d[3], DOTSCALE, b1v), 0.f);
        }
    }
    __syncthreads();

    {
        const int r0 = wid * 8;
        const int c0 = lane * 4;
        u64 acc[4][4];
        #pragma unroll
        for (int i = 0; i < 4; i++) { acc[i][0]=0; acc[i][1]=0; acc[i][2]=0; acc[i][3]=0; }
        #pragma unroll 4
        for (int k = 0; k < DIMC; k++) {
            const ulonglong2 aA = *(const ulonglong2*)(h2S + k * 132 + r0);
            const ulonglong2 aB = *(const ulonglong2*)(h2S + k * 132 + r0 + 4);
            const float4 w = *(const float4*)(ew3 + (size_t)k * DIMC + c0);
            const u64 wd[4] = {dup2(w.x), dup2(w.y), dup2(w.z), dup2(w.w)};
            const u64 av[4] = {aA.x, aA.y, aB.x, aB.y};
            #pragma unroll
            for (int i = 0; i < 4; i++) {
                ffma2(acc[i][0], av[i], wd[0]);
                ffma2(acc[i][1], av[i], wd[1]);
                ffma2(acc[i][2], av[i], wd[2]);
                ffma2(acc[i][3], av[i], wd[3]);
            }
        }
        const float4 b = *(const float4*)(eb3 + c0);
        const float bv[4] = {b.x, b.y, b.z, b.w};
        #pragma unroll
        for (int j = 0; j < 4; j++) {
            float o[8];
            #pragma unroll
            for (int i = 0; i < 4; i++) {
                float2 p = unpk(acc[i][j]);
                o[2 * i]     = p.x + bv[j];
                o[2 * i + 1] = p.y + bv[j];
            }
            *(float4*)(zeS + (c0 + j) * 132 + r0)     = make_float4(o[0], o[1], o[2], o[3]);
            *(float4*)(zeS + (c0 + j) * 132 + r0 + 4) = make_float4(o[4], o[5], o[6], o[7]);
        }
    }
    __syncthreads();

    if (tid < EROWS) {
        float s = 0.f, a = 0.f;
        #pragma unroll 4
        for (int d = 0; d < DIMC; d++) {
            float z = zeS[d * 132 + tid];
            s = fmaf(z, z, s);
            a += fabsf(z);
        }
        g_znorm[rbase + tid] = s;
        g_zabs[rbase + tid]  = a;
    }
    const size_t B = (size_t)nrows;
    float* out_ze = out + B * XD;
    for (int e = tid; e < EROWS * DIMC; e += ETHR) {
        int r = e >> 7, d = e & 127;
        float z = zeS[d * 132 + r];
        out_ze[(size_t)(rbase + r) * DIMC + d] = z;
        g_ze[(size_t)(rbase + r) * DIMC + d]   = z;
    }
}

// ---------------- VQ kernel (R12 + top-2 gap flag) ----------------
// smem: 0 finalS u64[64] | 512 margS | 768 bestU | 1024 cntS | 1280 candS (8192)
//       9472 candDm u32[64*32] (8192) | 17664 secondU u32[64] (256)
//       17920 zhS (17408) | 35328 chB0 | 70144 chB1 | end 104960
#define VQ_SMEM 104960

__global__ void __launch_bounds__(VTHR, 2) vq_kernel(
    const float* __restrict__ cb, float* __restrict__ out, int nrows)
{
    extern __shared__ char smc[];
    u64*   finalS  = (u64*)(smc);
    float* margS   = (float*)(smc + 512);
    u32*   bestU   = (u32*)(smc + 768);
    u32*   cntS    = (u32*)(smc + 1024);
    u32*   candS   = (u32*)(smc + 1280);
    u32*   candDm  = (u32*)(smc + 9472);
    u32*   secondU = (u32*)(smc + 17664);
    u32*   zhS     = (u32*)(smc + 17920);
    u32*   chB     = (u32*)(smc + 35328);

    const int tid  = threadIdx.x;
    const int wid  = tid >> 5, lane = tid & 31;
    const int g    = lane >> 2, tg = lane & 3;
    const int rbase = blockIdx.x * VROWS;

    const int mbase = (wid >> 2) * 32;
    const int nq    = (wid & 3) * 32;

    const u32 chBase = smem_u32(chB);

    {
        const char* src = (const char*)g_ch16;
        #pragma unroll
        for (int t = 0; t < 8; t++) {
            int i = t * VTHR + tid;
            u32 dst = chBase + ((u32)(i >> 4) * APW + (u32)(i & 15) * 4) * 4;
            cp16(dst, src + (size_t)i * 16);
        }
        CP_COMMIT();
    }

    for (int i = tid; i < VROWS; i += VTHR) {
        bestU[i]   = 0xFFFFFFFFu;
        finalS[i]  = ~0ull;
        cntS[i]    = 0u;
        secondU[i] = 0xFFFFFFFFu;
        margS[i]   = g_zabs[rbase + i] * 4.0e-6f + 4.0e-6f;
    }

    for (int i = tid; i < VROWS * 64; i += VTHR) {
        int r = i >> 6, c = i & 63;
        float2 z = *(const float2*)(g_ze + (size_t)(rbase + r) * DIMC + c * 2);
        __half2 hp(__float2half_rn(z.x), __float2half_rn(z.y));
        zhS[r * APW + c] = *(u32*)&hp;
    }
    CP_WAIT0();
    __syncthreads();

    const int r0 = mbase + g;
    const float mg0 = margS[r0], mg1 = margS[r0 + 8];
    const float mg2 = margS[r0 + 16], mg3 = margS[r0 + 24];

    float dacc[2][4][4];

    for (int q = 0; q < NCHUNK; q++) {
        u32* chD = chB + (u32)(q & 1) * (CHBYTES / 4);

        if (q < NCHUNK - 1) {
            const char* src = (const char*)(g_ch16 + (size_t)(q + 1) * CHN * DIMC);
            const u32 dstBase = chBase + (u32)((q + 1) & 1) * CHBYTES;
            #pragma unroll
            for (int t = 0; t < 8; t++) {
                int i = t * VTHR + tid;
                u32 dst = dstBase + ((u32)(i >> 4) * APW + (u32)(i & 15) * 4) * 4;
                cp16(dst, src + (size_t)i * 16);
            }
            CP_COMMIT();
        }

        #pragma unroll
        for (int mt = 0; mt < 2; mt++)
            #pragma unroll
            for (int nt = 0; nt < 4; nt++) {
                dacc[mt][nt][0] = 0.f; dacc[mt][nt][1] = 0.f;
                dacc[mt][nt][2] = 0.f; dacc[mt][nt][3] = 0.f;
            }

        #pragma unroll
        for (int kt = 0; kt < 8; kt++) {
            const int ka = kt * 8 + tg;
            u32 a[2][4];
            #pragma unroll
            for (int mt = 0; mt < 2; mt++) {
                const int rb = (mbase + mt * 16 + g) * APW;
                a[mt][0] = zhS[rb + ka];
                a[mt][1] = zhS[rb + 8 * APW + ka];
                a[mt][2] = zhS[rb + ka + 4];
                a[mt][3] = zhS[rb + 8 * APW + ka + 4];
            }
            #pragma unroll
            for (int nt = 0; nt < 4; nt++) {
                const int w = (nq + nt * 8 + g) * APW + ka;
                const u32 b0 = chD[w], b1 = chD[w + 4];
                mma16816(dacc[0][nt], a[0][0], a[0][1], a[0][2], a[0][3], b0, b1);
                mma16816(dacc[1][nt], a[1][0], a[1][1], a[1][2], a[1][3], b0, b1);
            }
        }

        u32 mn0 = ~0u, mn1 = ~0u, mn2 = ~0u, mn3 = ~0u;
        #pragma unroll
        for (int mt = 0; mt < 2; mt++)
            #pragma unroll
            for (int nt = 0; nt < 4; nt++) {
                const int jb = q * CHN + nq + nt * 8 + 2 * tg;
                const float cn0 = __ldg(g_cnorm + jb);
                const float cn1 = __ldg(g_cnorm + jb + 1);
                float* d = dacc[mt][nt];
                float s0 = fmaf(d[0], -2.0f * DOTSCALE, cn0);
                float s1 = fmaf(d[1], -2.0f * DOTSCALE, cn1);
                float s2 = fmaf(d[2], -2.0f * DOTSCALE, cn0);
                float s3 = fmaf(d[3], -2.0f * DOTSCALE, cn1);
                d[0] = s0; d[1] = s1; d[2] = s2; d[3] = s3;
                u32 ma = min(fmap(s0), fmap(s1));
                u32 mb = min(fmap(s2), fmap(s3));
                if (mt == 0) { mn0 = min(mn0, ma); mn1 = min(mn1, mb); }
                else         { mn2 = min(mn2, ma); mn3 = min(mn3, mb); }
            }
        atomicMin(&bestU[r0],      mn0);
        atomicMin(&bestU[r0 + 8],  mn1);
        atomicMin(&bestU[r0 + 16], mn2);
        atomicMin(&bestU[r0 + 24], mn3);
        __syncthreads();

        const float t0 = finv(bestU[r0])      + mg0;
        const float t1 = finv(bestU[r0 + 8])  + mg1;
        const float t2 = finv(bestU[r0 + 16]) + mg2;
        const float t3 = finv(bestU[r0 + 24]) + mg3;

        #pragma unroll
        for (int mt = 0; mt < 2; mt++) {
            const int rA = r0 + mt * 16, rB = rA + 8;
            const float tA = mt ? t2 : t0;
            const float tB = mt ? t3 : t1;
            #pragma unroll
            for (int nt = 0; nt < 4; nt++) {
                const int jb = q * CHN + nq + nt * 8 + 2 * tg;
                const float* d = dacc[mt][nt];
                if (d[0] <= tA) {
                    u32 p = atomicAdd(&cntS[rA], 1u);
                    if (p < CAND_MAX) candS[rA * CAND_MAX + p] = (u32)jb;
                }
                if (d[1] <= tA) {
                    u32 p = atomicAdd(&cntS[rA], 1u);
                    if (p < CAND_MAX) candS[rA * CAND_MAX + p] = (u32)(jb + 1);
                }
                if (d[2] <= tB) {
                    u32 p = atomicAdd(&cntS[rB], 1u);
                    if (p < CAND_MAX) candS[rB * CAND_MAX + p] = (u32)jb;
                }
                if (d[3] <= tB) {
                    u32 p = atomicAdd(&cntS[rB], 1u);
                    if (p < CAND_MAX) candS[rB * CAND_MAX + p] = (u32)(jb + 1);
                }
            }
        }

        if (q < NCHUNK - 1) CP_WAIT0();
        __syncthreads();
    }

    // ---- exact fp32 refine; store per-candidate exact distance keys ----
    {
        const int rr = tid >> 2, c4 = tid & 3;
        const float zn = g_znorm[rbase + rr];
        const float* zp = g_ze + (size_t)(rbase + rr) * DIMC;
        int cnt = (int)cntS[rr];
        if (cnt <= CAND_MAX) {
            for (int c = c4; c < cnt; c += 4) {
                int j = (int)candS[rr * CAND_MAX + c];
                const float* cp = cb + (size_t)j * DIMC;
                float dot = 0.f;
                #pragma unroll 8
                for (int d = 0; d < DIMC; d++) dot = fmaf(zp[d], cp[d], dot);
                float dvv = (zn - 2.0f * dot) + __ldg(g_cnorm + j);
                u32 m = fmap(dvv);
                candDm[rr * CAND_MAX + c] = m;
                u64 key = ((u64)m << 32) | (u32)j;
                atomicMin(&finalS[rr], key);
            }
        } else {
            for (int j = c4; j < KC; j += 4) {
                const float* cp = cb + (size_t)j * DIMC;
                float dot = 0.f;
                #pragma unroll 8
                for (int d = 0; d < DIMC; d++) dot = fmaf(zp[d], cp[d], dot);
                float dvv = (zn - 2.0f * dot) + __ldg(g_cnorm + j);
                u64 key = ((u64)fmap(dvv) << 32) | (u32)j;
                atomicMin(&finalS[rr], key);
            }
        }
    }
    __syncthreads();

    // ---- second-best pass (only valid for non-overflow rows) ----
    {
        const int rr = tid >> 2, c4 = tid & 3;
        int cnt = (int)cntS[rr];
        if (cnt >= 2 && cnt <= CAND_MAX) {
            const u64 best = finalS[rr];
            for (int c = c4; c < cnt; c += 4) {
                u32 m = candDm[rr * CAND_MAX + c];
                u32 j = candS[rr * CAND_MAX + c];
                u64 key = ((u64)m << 32) | j;
                if (key != best) atomicMin(&secondU[rr], m);
            }
        }
    }
    __syncthreads();

    if (tid < VROWS) {
        int idx = (int)(finalS[tid] & 0xFFFFFFFFull);
        g_idx[rbase + tid] = idx;
        float* out_id = out + (size_t)nrows * XD + (size_t)nrows * DIMC * 2;
        out_id[rbase + tid] = (float)idx;

        // flag near-tie / overflow rows for exact repair
        int cnt = (int)cntS[tid];
        bool flag;
        if (cnt > CAND_MAX) {
            flag = true;
        } else if (cnt >= 2) {
            float db = finv((u32)(finalS[tid] >> 32));
            float ds = finv(secondU[tid]);
            flag = (ds - db) < REPAIR_GAP;
        } else {
            flag = false;
        }
        if (flag) {
            int pos = atomicAdd(&g_rcnt, 1);
            g_rlist[pos] = rbase + tid;
        }
    }
}

// ---------------- repair kernel: exact fp32 enc + full argmin ---------------
__global__ void __launch_bounds__(256, 4) repair_kernel(
    const float* __restrict__ state, const float* __restrict__ x,
    const float* __restrict__ cb,
    const float* __restrict__ ew1, const float* __restrict__ eb1,
    const float* __restrict__ ew2, const float* __restrict__ eb2,
    const float* __restrict__ ew3, const float* __restrict__ eb3,
    float* __restrict__ out, int nrows)
{
    __shared__ float inS[264];
    __shared__ float h1S[128];
    __shared__ float h2S[128];
    __shared__ float zeS[128];
    __shared__ float znS;
    __shared__ u64 bkey;

    const int tid = threadIdx.x;
    const int total = g_rcnt;

    for (int it = blockIdx.x; it < total; it += gridDim.x) {
        const int row = g_rlist[it];
        __syncthreads();   // protect smem reuse across iterations

        for (int i = tid; i < 264; i += 256)
            inS[i] = (i < SDIM) ? state[(size_t)row * SDIM + i]
                                : x[(size_t)row * XD + (i - SDIM)];
        __syncthreads();

        if (tid < 128) {
            float s = eb1[tid];
            for (int k = 0; k < 264; k++) s = fmaf(inS[k], ew1[(size_t)k * 128 + tid], s);
            h1S[tid] = fmaxf(s, 0.f);
        }
        __syncthreads();
        if (tid < 128) {
            float s = eb2[tid];
            for (int k = 0; k < 128; k++) s = fmaf(h1S[k], ew2[(size_t)k * 128 + tid], s);
            h2S[tid] = fmaxf(s, 0.f);
        }
        __syncthreads();
        if (tid < 128) {
            float s = eb3[tid];
            for (int k = 0; k < 128; k++) s = fmaf(h2S[k], ew3[(size_t)k * 128 + tid], s);
            zeS[tid] = s;
        }
        __syncthreads();
        if (tid == 0) {
            float s = 0.f;
            for (int d = 0; d < 128; d++) s = fmaf(zeS[d], zeS[d], s);
            znS = s;
            bkey = ~0ull;
        }
        __syncthreads();

        {
            u64 lbest = ~0ull;
            for (int j = tid; j < KC; j += 256) {
                const float* cp = cb + (size_t)j * DIMC;
                float dot = 0.f;
                #pragma unroll 8
                for (int d = 0; d < DIMC; d++) dot = fmaf(zeS[d], cp[d], dot);
                float dvv = (znS - 2.0f * dot) + __ldg(g_cnorm + j);
                u64 key = ((u64)fmap(dvv) << 32) | (u32)j;
                if (key < lbest) lbest = key;
            }
            atomicMin(&bkey, lbest);
        }
        __syncthreads();

        // overwrite outputs for this row
        const size_t B = (size_t)nrows;
        float* out_ze = out + B * XD;
        float* out_id = out + B * XD + B * (size_t)DIMC * 2;
        if (tid < 128) {
            g_ze[(size_t)row * DIMC + tid] = zeS[tid];
            out_ze[(size_t)row * DIMC + tid] = zeS[tid];
        }
        if (tid == 0) {
            int idx = (int)(bkey & 0xFFFFFFFFull);
            g_idx[row] = idx;
            out_id[row] = (float)idx;
        }
    }
}

// ---------------- decoder (R9/R12: fp16 3-term split) ------------------------
#define DEC_SMEM 139264

__global__ void __launch_bounds__(DTHR, 1) dec_kernel(
    const float* __restrict__ state, const float* __restrict__ cb,
    const float* __restrict__ db1, const float* __restrict__ db2,
    const float* __restrict__ dw3, const float* __restrict__ db3,
    float* __restrict__ out, int nrows)
{
    extern __shared__ char smc[];
    u32* xhS = (u32*)(smc);
    u32* xlS = (u32*)(smc + 34816);
    u32* whS = (u32*)(smc + 69632);
    u32* wlS = (u32*)(smc + 104448);
    float* h2S = (float*)(smc + 69632);

    const int tid  = threadIdx.x;
    const int wid  = tid >> 5, lane = tid & 31;
    const int g    = lane >> 2, tg = lane & 3;
    const int rbase = blockIdx.x * DROWS;

    const int mbase = (wid >> 2) * 32;
    const int nq    = (wid & 3) * 32;

    const size_t B = (size_t)nrows;
    float* out_xt = out;
    float* out_zq = out + B * XD + B * (size_t)DIMC;

    float dacc[2][4][4];
    #pragma unroll
    for (int mt = 0; mt < 2; mt++)
        #pragma unroll
        for (int nt = 0; nt < 4; nt++) {
            dacc[mt][nt][0] = 0.f; dacc[mt][nt][1] = 0.f;
            dacc[mt][nt][2] = 0.f; dacc[mt][nt][3] = 0.f;
        }

    for (int ch = 0; ch < 3; ch++) {
        if (ch < 2) {
            for (int i = tid; i < DROWS * 64; i += DTHR) {
                int r = i >> 6, cw = i & 63;
                float2 v = *(const float2*)(state + (size_t)(rbase + r) * SDIM + ch * 128 + 2 * cw);
                float v0 = v.x * 16.0f, v1 = v.y * 16.0f;
                __half h0 = __float2half_rn(v0), h1 = __float2half_rn(v1);
                __half l0 = __float2half_rn(v0 - __half2float(h0));
                __half l1 = __float2half_rn(v1 - __half2float(h1));
                __half2 hp(h0, h1), lp(l0, l1);
                xhS[r * APW + cw] = *(u32*)&hp;
                xlS[r * APW + cw] = *(u32*)&lp;
            }
        } else {
            for (int i = tid; i < DROWS * 64; i += DTHR) {
                int r = i >> 6, cw = i & 63;
                int d = 2 * cw;
                float2 z = *(const float2*)(g_ze + (size_t)(rbase + r) * DIMC + d);
                int idx = g_idx[rbase + r];
                float2 q = *(const float2*)(cb + (size_t)idx * DIMC + d);
                *(float2*)(out_zq + (size_t)(rbase + r) * DIMC + d) = q;
                float v0 = (z.x + (q.x - z.x)) * 16.0f;
                float v1 = (z.y + (q.y - z.y)) * 16.0f;
                __half h0 = __float2half_rn(v0), h1 = __float2half_rn(v1);
                __half l0 = __float2half_rn(v0 - __half2float(h0));
                __half l1 = __float2half_rn(v1 - __half2float(h1));
                __half2 hp(h0, h1), lp(l0, l1);
                xhS[r * APW + cw] = *(u32*)&hp;
                xlS[r * APW + cw] = *(u32*)&lp;
            }
        }
        {
            const u32* srcH = (const u32*)g_w1h;
            const u32* srcL = (const u32*)g_w1l;
            for (int i = tid; i < 128 * 64; i += DTHR) {
                int n = i >> 6, cw = i & 63;
                int woff = n * 192 + ch * 64 + cw;
                whS[n * APW + cw] = srcH[woff];
                wlS[n * APW + cw] = srcL[woff];
            }
        }
        __syncthreads();

        #pragma unroll
        for (int kt = 0; kt < 8; kt++) {
            const int ka = kt * 8 + tg;
            u32 ah[2][4], al[2][4];
            #pragma unroll
            for (int mt = 0; mt < 2; mt++) {
                const int rb = (mbase + mt * 16 + g) * APW;
                ah[mt][0] = xhS[rb + ka];
                ah[mt][1] = xhS[rb + 8 * APW + ka];
                ah[mt][2] = xhS[rb + ka + 4];
                ah[mt][3] = xhS[rb + 8 * APW + ka + 4];
                al[mt][0] = xlS[rb + ka];
                al[mt][1] = xlS[rb + 8 * APW + ka];
                al[mt][2] = xlS[rb + ka + 4];
                al[mt][3] = xlS[rb + 8 * APW + ka + 4];
            }
            #pragma unroll
            for (int nt = 0; nt < 4; nt++) {
                const int w = (nq + nt * 8 + g) * APW + ka;
                const u32 bh0 = whS[w], bh1 = whS[w + 4];
                const u32 bl0 = wlS[w], bl1 = wlS[w + 4];
                #pragma unroll
                for (int mt = 0; mt < 2; mt++) {
                    mma16816(dacc[mt][nt], ah[mt][0], ah[mt][1], ah[mt][2], ah[mt][3], bh0, bh1);
                    mma16816(dacc[mt][nt], al[mt][0], al[mt][1], al[mt][2], al[mt][3], bh0, bh1);
                    mma16816(dacc[mt][nt], ah[mt][0], ah[mt][1], ah[mt][2], ah[mt][3], bl0, bl1);
                }
            }
        }
        __syncthreads();
    }

    #pragma unroll
    for (int mt = 0; mt < 2; mt++) {
        const int rA = mbase + mt * 16 + g, rB = rA + 8;
        #pragma unroll
        for (int nt = 0; nt < 4; nt++) {
            const int jb = nq + nt * 8 + 2 * tg;
            const float b0v = __ldg(db1 + jb), b1v = __ldg(db1 + jb + 1);
            float* d = dacc[mt][nt];
            float s0 = fmaxf(fmaf(d[0], DOTSCALE, b0v), 0.f) * 16.0f;
            float s1 = fmaxf(fmaf(d[1], DOTSCALE, b1v), 0.f) * 16.0f;
            float s2 = fmaxf(fmaf(d[2], DOTSCALE, b0v), 0.f) * 16.0f;
            float s3 = fmaxf(fmaf(d[3], DOTSCALE, b1v), 0.f) * 16.0f;
            const int w = (nq >> 1) + nt * 4 + tg;
            __half h0 = __float2half_rn(s0), h1 = __float2half_rn(s1);
            __half l0 = __float2half_rn(s0 - __half2float(h0));
            __half l1 = __float2half_rn(s1 - __half2float(h1));
            __half2 hpA(h0, h1), lpA(l0, l1);
            xhS[rA * APW + w] = *(u32*)&hpA;
            xlS[rA * APW + w] = *(u32*)&lpA;
            __half h2 = __float2half_rn(s2), h3 = __float2half_rn(s3);
            __half l2 = __float2half_rn(s2 - __half2float(h2));
            __half l3 = __float2half_rn(s3 - __half2float(h3));
            __half2 hpB(h2, h3), lpB(l2, l3);
            xhS[rB * APW + w] = *(u32*)&hpB;
            xlS[rB * APW + w] = *(u32*)&lpB;
        }
    }
    {
        const u32* srcH = (const u32*)g_w2h;
        const u32* srcL = (const u32*)g_w2l;
        for (int i = tid; i < 128 * 64; i += DTHR) {
            int n = i >> 6, cw = i & 63;
            whS[n * APW + cw] = srcH[n * 64 + cw];
            wlS[n * APW + cw] = srcL[n * 64 + cw];
        }
    }
    __syncthreads();

    #pragma unroll
    for (int mt = 0; mt < 2; mt++)
        #pragma unroll
        for (int nt = 0; nt < 4; nt++) {
            dacc[mt][nt][0] = 0.f; dacc[mt][nt][1] = 0.f;
            dacc[mt][nt][2] = 0.f; dacc[mt][nt][3] = 0.f;
        }
    #pragma unroll
    for (int kt = 0; kt < 8; kt++) {
        const int ka = kt * 8 + tg;
        u32 ah[2][4], al[2][4];
        #pragma unroll
        for (int mt = 0; mt < 2; mt++) {
            const int rb = (mbase + mt * 16 + g) * APW;
            ah[mt][0] = xhS[rb + ka];
            ah[mt][1] = xhS[rb + 8 * APW + ka];
            ah[mt][2] = xhS[rb + ka + 4];
            ah[mt][3] = xhS[rb + 8 * APW + ka + 4];
            al[mt][0] = xlS[rb + ka];
            al[mt][1] = xlS[rb + 8 * APW + ka];
            al[mt][2] = xlS[rb + ka + 4];
            al[mt][3] = xlS[rb + 8 * APW + ka + 4];
        }
        #pragma unroll
        for (int nt = 0; nt < 4; nt++) {
            const int w = (nq + nt * 8 + g) * APW + ka;
            const u32 bh0 = whS[w], bh1 = whS[w + 4];
            const u32 bl0 = wlS[w], bl1 = wlS[w + 4];
            #pragma unroll
            for (int mt = 0; mt < 2; mt++) {
                mma16816(dacc[mt][nt], ah[mt][0], ah[mt][1], ah[mt][2], ah[mt][3], bh0, bh1);
                mma16816(dacc[mt][nt], al[mt][0], al[mt][1], al[mt][2], al[mt][3], bh0, bh1);
                mma16816(dacc[mt][nt], ah[mt][0], ah[mt][1], ah[mt][2], ah[mt][3], bl0, bl1);
            }
        }
    }
    __syncthreads();

    #pragma unroll
    for (int mt = 0; mt < 2; mt++) {
        const int rA = mbase + mt * 16 + g, rB = rA + 8;
        #pragma unroll
        for (int nt = 0; nt < 4; nt++) {
            const int jb = nq + nt * 8 + 2 * tg;
            const float b0v = __ldg(db2 + jb), b1v = __ldg(db2 + jb + 1);
            float* d = dacc[mt][nt];
            h2S[jb * 132 + rA]       = fmaxf(fmaf(d[0], DOTSCALE, b0v), 0.f);
            h2S[(jb + 1) * 132 + rA] = fmaxf(fmaf(d[1], DOTSCALE, b1v), 0.f);
            h2S[jb * 132 + rB]       = fmaxf(fmaf(d[2], DOTSCALE, b0v), 0.f);
            h2S[(jb + 1) * 132 + rB] = fmaxf(fmaf(d[3], DOTSCALE, b1v), 0.f);
        }
    }
    __syncthreads();

    {
        int r = tid & 127;
        int c = (tid >> 7) * 2;
        float a0 = 0.f, a1 = 0.f;
        #pragma unroll 4
        for (int d = 0; d < DIMC; d++) {
            float h = h2S[d * 132 + r];
            a0 = fmaf(h, dw3[d * XD + c],     a0);
            a1 = fmaf(h, dw3[d * XD + c + 1], a1);
        }
        out_xt[(size_t)(rbase + r) * XD + c]     = a0 + db3[c];
        out_xt[(size_t)(rbase + r) * XD + c + 1] = a1 + db3[c + 1];
    }
}

// ---------------- launch ----------------
extern "C" void kernel_launch(void* const* d_in, const int* in_sizes, int n_in,
                              void* d_out, int out_size) {
    const float* state = (const float*)d_in[0];
    const float* x     = (const float*)d_in[1];
    const float* cb    = (const float*)d_in[2];
    const float* ew1   = (const float*)d_in[3];
    const float* eb1   = (const float*)d_in[4];
    const float* ew2   = (const float*)d_in[5];
    const float* eb2   = (const float*)d_in[6];
    const float* ew3   = (const float*)d_in[7];
    const float* eb3   = (const float*)d_in[8];
    const float* dw1   = (const float*)d_in[9];
    const float* db1   = (const float*)d_in[10];
    const float* dw2   = (const float*)d_in[11];
    const float* db2   = (const float*)d_in[12];
    const float* dw3   = (const float*)d_in[13];
    const float* db3   = (const float*)d_in[14];

    const int nrows = in_sizes[0] / SDIM;   // 262144

    static bool attrs_set = false;
    if (!attrs_set) {
        cudaFuncSetAttribute((const void*)enc_kernel, cudaFuncAttributeMaxDynamicSharedMemorySize, ENC_SMEM);
        cudaFuncSetAttribute((const void*)vq_kernel,  cudaFuncAttributeMaxDynamicSharedMemorySize, VQ_SMEM);
        cudaFuncSetAttribute((const void*)dec_kernel, cudaFuncAttributeMaxDynamicSharedMemorySize, DEC_SMEM);
        attrs_set = true;
    }

    vq_prep<<<KC, DIMC>>>(cb);
    dec_prep<<<(128 * 384 + 128 * 128 + 255) / 256, 256>>>(dw1, dw2);
    enc_prep<<<(128 * 272 + 128 * 128 + 255) / 256, 256>>>(ew1, ew2);
    enc_kernel<<<nrows / EROWS, ETHR, ENC_SMEM>>>(state, x, eb1, eb2, ew3, eb3,
                                                  (float*)d_out, nrows);
    vq_kernel<<<nrows / VROWS, VTHR, VQ_SMEM>>>(cb, (float*)d_out, nrows);
    repair_kernel<<<2048, 256>>>(state, x, cb, ew1, eb1, ew2, eb2, ew3, eb3,
                                 (float*)d_out, nrows);
    dec_kernel<<<nrows / DROWS, DTHR, DEC_SMEM>>>(state, cb, db1, db2, dw3, db3,
                                                  (float*)d_out, nrows);
}

// round 16
// speedup vs baseline: 3.0119x; 3.0119x over previous
#include <cuda_runtime.h>
#include <cuda_fp16.h>
#include <cstdint>

typedef unsigned long long u64;
typedef unsigned int u32;

#define PITCH   68
#define ROWS    64
#define NTHR    256
#define DIMC    128
#define KC      1024
#define SDIM    256
#define XD      8
#define BTOT    262144

#define VROWS   64
#define VTHR    256
#define NCHUNK  8
#define CHN     128
#define CAND_MAX 32
#define APW     68
#define DOTSCALE 0.0009765625f   // 2^-10 exact
#define CHBYTES 34816

#define DROWS   64
#define DTHR    256

// ---------------- scratch globals ----------------
__device__ float   g_cnorm[KC];
__device__ __half  g_ch16[KC * DIMC];       // fp16(codebook * 1024)
__device__ float   g_ze[(size_t)BTOT * DIMC];
__device__ float   g_znorm[BTOT];
__device__ float   g_zabs[BTOT];
__device__ int     g_idx[BTOT];
__device__ __half  g_w1h[128 * 384];        // dec w1^T * 64 (hi/lo)
__device__ __half  g_w1l[128 * 384];
__device__ __half  g_w2h[128 * 128];
__device__ __half  g_w2l[128 * 128];

// ---------------- prep ----------------
__global__ void vq_prep(const float* __restrict__ cb) {
    int j = blockIdx.x;
    int d = threadIdx.x;
    float v = cb[j * DIMC + d];
    g_ch16[j * DIMC + d] = __float2half_rn(v * 1024.0f);
    __shared__ float red[DIMC];
    red[d] = v * v;
    __syncthreads();
    #pragma unroll
    for (int s = 64; s > 0; s >>= 1) {
        if (d < s) red[d] += red[d + s];
        __syncthreads();
    }
    if (d == 0) g_cnorm[j] = red[0];
}

__global__ void dec_prep(const float* __restrict__ dw1, const float* __restrict__ dw2) {
    int i = blockIdx.x * 256 + threadIdx.x;
    if (i < 128 * 384) {
        int n = i / 384, k = i % 384;
        float v = dw1[k * 128 + n] * 64.0f;
        __half h = __float2half_rn(v);
        g_w1h[i] = h;
        g_w1l[i] = __float2half_rn(v - __half2float(h));
    } else if (i < 128 * 384 + 128 * 128) {
        int j = i - 128 * 384;
        int n = j / 128, k = j % 128;
        float v = dw2[k * 128 + n] * 64.0f;
        __half h = __float2half_rn(v);
        g_w2h[j] = h;
        g_w2l[j] = __float2half_rn(v - __half2float(h));
    }
}

// ---------------- packed f32x2 helpers ----------------
__device__ __forceinline__ u64 dup2(float w) {
    u64 r; unsigned u = __float_as_uint(w);
    asm("mov.b64 %0, {%1, %1};" : "=l"(r) : "r"(u));
    return r;
}
__device__ __forceinline__ void ffma2(u64& d, u64 a, u64 b) {
    asm("fma.rn.f32x2 %0, %1, %2, %0;" : "+l"(d) : "l"(a), "l"(b));
}
__device__ __forceinline__ float2 unpk(u64 v) {
    unsigned lo, hi;
    asm("mov.b64 {%0, %1}, %2;" : "=r"(lo), "=r"(hi) : "l"(v));
    return make_float2(__uint_as_float(lo), __uint_as_float(hi));
}

// ---------------- fp32 gemm (accumulate + store split) ----------------
__device__ __forceinline__ void gemm_accum(
    const float* __restrict__ inS, int Kdim,
    const float* __restrict__ W, u64 (&acc)[4][4], int warp, int lane)
{
    const int r0 = warp * 8;
    const int c0 = lane * 4;
    #pragma unroll 4
    for (int k = 0; k < Kdim; k++) {
        const ulonglong2 aA = *(const ulonglong2*)(inS + k * PITCH + r0);
        const ulonglong2 aB = *(const ulonglong2*)(inS + k * PITCH + r0 + 4);
        const float4 w = *(const float4*)(W + (size_t)k * DIMC + c0);
        const u64 wd[4] = {dup2(w.x), dup2(w.y), dup2(w.z), dup2(w.w)};
        const u64 av[4] = {aA.x, aA.y, aB.x, aB.y};
        #pragma unroll
        for (int i = 0; i < 4; i++) {
            ffma2(acc[i][0], av[i], wd[0]);
            ffma2(acc[i][1], av[i], wd[1]);
            ffma2(acc[i][2], av[i], wd[2]);
            ffma2(acc[i][3], av[i], wd[3]);
        }
    }
}
__device__ __forceinline__ void gemm_store(
    u64 (&acc)[4][4], const float* __restrict__ bias,
    float* __restrict__ outS, bool relu, int warp, int lane)
{
    const int r0 = warp * 8;
    const int c0 = lane * 4;
    const float4 b = *(const float4*)(bias + c0);
    const float bv[4] = {b.x, b.y, b.z, b.w};
    #pragma unroll
    for (int j = 0; j < 4; j++) {
        float o[8];
        #pragma unroll
        for (int i = 0; i < 4; i++) {
            float2 p = unpk(acc[i][j]);
            float v0 = p.x + bv[j];
            float v1 = p.y + bv[j];
            o[2 * i]     = relu ? fmaxf(v0, 0.f) : v0;
            o[2 * i + 1] = relu ? fmaxf(v1, 0.f) : v1;
        }
        *(float4*)(outS + (c0 + j) * PITCH + r0)     = make_float4(o[0], o[1], o[2], o[3]);
        *(float4*)(outS + (c0 + j) * PITCH + r0 + 4) = make_float4(o[4], o[5], o[6], o[7]);
    }
}
#define ACC_ZERO(acc) do { _Pragma("unroll") \
    for (int _i = 0; _i < 4; _i++) { acc[_i][0]=0; acc[_i][1]=0; acc[_i][2]=0; acc[_i][3]=0; } } while (0)

// ---------------- encoder (R7/R12: fp32, k-chunked, 3 CTAs/SM) ---------------
__global__ void __launch_bounds__(NTHR, 3) enc_kernel(
    const float* __restrict__ state, const float* __restrict__ x,
    const float* __restrict__ ew1, const float* __restrict__ eb1,
    const float* __restrict__ ew2, const float* __restrict__ eb2,
    const float* __restrict__ ew3, const float* __restrict__ eb3,
    float* __restrict__ out, int nrows)
{
    extern __shared__ float sm[];
    float* X  = sm;                      // [136][PITCH] staging / h2
    float* hA = sm + 136 * PITCH;        // [128][PITCH]

    const int tid  = threadIdx.x;
    const int warp = tid >> 5, lane = tid & 31;
    const int rbase = blockIdx.x * ROWS;

    u64 acc[4][4];
    ACC_ZERO(acc);

    for (int e = tid; e < ROWS * 128; e += NTHR) {
        int r = e >> 7, k = e & 127;
        X[k * PITCH + r] = state[(size_t)(rbase + r) * SDIM + k];
    }
    __syncthreads();
    gemm_accum(X, 128, ew1, acc, warp, lane);
    __syncthreads();

    for (int e = tid; e < ROWS * 128; e += NTHR) {
        int r = e >> 7, k = e & 127;
        X[k * PITCH + r] = state[(size_t)(rbase + r) * SDIM + 128 + k];
    }
    for (int e = tid; e < ROWS * XD; e += NTHR) {
        int r = e >> 3, k = e & 7;
        X[(128 + k) * PITCH + r] = x[(size_t)(rbase + r) * XD + k];
    }
    __syncthreads();
    gemm_accum(X, 136, ew1 + (size_t)128 * DIMC, acc, warp, lane);
    gemm_store(acc, eb1, hA, true, warp, lane);
    __syncthreads();

    ACC_ZERO(acc);
    gemm_accum(hA, DIMC, ew2, acc, warp, lane);
    gemm_store(acc, eb2, X, true, warp, lane);
    __syncthreads();

    ACC_ZERO(acc);
    gemm_accum(X, DIMC, ew3, acc, warp, lane);
    gemm_store(acc, eb3, hA, false, warp, lane);   // z_e -> hA
    __syncthreads();

    if (tid < ROWS) {
        float s = 0.f, a = 0.f;
        #pragma unroll 4
        for (int d = 0; d < DIMC; d++) {
            float z = hA[d * PITCH + tid];
            s = fmaf(z, z, s);
            a += fabsf(z);
        }
        g_znorm[rbase + tid] = s;
        g_zabs[rbase + tid]  = a;
    }

    const size_t B = (size_t)nrows;
    float* out_ze = out + B * XD;
    for (int e = tid; e < ROWS * DIMC; e += NTHR) {
        int r = e >> 7, d = e & 127;
        float z = hA[d * PITCH + r];
        out_ze[(size_t)(rbase + r) * DIMC + d] = z;
        g_ze[(size_t)(rbase + r) * DIMC + d]   = z;
    }
}

// ---------------- fp16 mma + cp.async helpers ----------------
__device__ __forceinline__ void mma16816(float* d, u32 a0, u32 a1, u32 a2, u32 a3,
                                         u32 b0, u32 b1) {
    asm volatile(
        "mma.sync.aligned.m16n8k16.row.col.f32.f16.f16.f32 "
        "{%0,%1,%2,%3}, {%4,%5,%6,%7}, {%8,%9}, {%0,%1,%2,%3};"
        : "+f"(d[0]), "+f"(d[1]), "+f"(d[2]), "+f"(d[3])
        : "r"(a0), "r"(a1), "r"(a2), "r"(a3), "r"(b0), "r"(b1));
}
__device__ __forceinline__ u32 smem_u32(const void* p) {
    u32 a;
    asm("{ .reg .u64 t; cvta.to.shared.u64 t, %1; cvt.u32.u64 %0, t; }" : "=r"(a) : "l"(p));
    return a;
}
__device__ __forceinline__ void cp16(u32 dst, const void* src) {
    asm volatile("cp.async.cg.shared.global [%0], [%1], 16;" :: "r"(dst), "l"(src) : "memory");
}
#define CP_COMMIT() asm volatile("cp.async.commit_group;" ::: "memory")
#define CP_WAIT0()  asm volatile("cp.async.wait_group 0;" ::: "memory")

__device__ __forceinline__ u32 fmap(float f) {
    u32 u = __float_as_uint(f);
    return (u & 0x80000000u) ? ~u : (u | 0x80000000u);
}
__device__ __forceinline__ float finv(u32 m) {
    u32 u = (m & 0x80000000u) ? (m ^ 0x80000000u) : ~m;
    return __uint_as_float(u);
}

// ---------------- VQ kernel (R12: fp16 screen + cp.async, 2 CTAs/SM) ---------
#define VQ_SMEM 96512

__global__ void __launch_bounds__(VTHR, 2) vq_kernel(
    const float* __restrict__ cb, float* __restrict__ out, int nrows)
{
    extern __shared__ char smc[];
    u64*   finalS = (u64*)(smc);
    float* margS  = (float*)(smc + 512);
    u32*   bestU  = (u32*)(smc + 768);
    u32*   cntS   = (u32*)(smc + 1024);
    u32*   candS  = (u32*)(smc + 1280);
    u32*   zhS    = (u32*)(smc + 9472);
    u32*   chB    = (u32*)(smc + 26880);

    const int tid  = threadIdx.x;
    const int wid  = tid >> 5, lane = tid & 31;
    const int g    = lane >> 2, tg = lane & 3;
    const int rbase = blockIdx.x * VROWS;

    const int mbase = (wid >> 2) * 32;
    const int nq    = (wid & 3) * 32;

    const u32 chBase = smem_u32(chB);

    {
        const char* src = (const char*)g_ch16;
        #pragma unroll
        for (int t = 0; t < 8; t++) {
            int i = t * VTHR + tid;
            u32 dst = chBase + ((u32)(i >> 4) * APW + (u32)(i & 15) * 4) * 4;
            cp16(dst, src + (size_t)i * 16);
        }
        CP_COMMIT();
    }

    for (int i = tid; i < VROWS; i += VTHR) {
        bestU[i]  = 0xFFFFFFFFu;
        finalS[i] = ~0ull;
        cntS[i]   = 0u;
        margS[i]  = g_zabs[rbase + i] * 4.0e-6f + 4.0e-6f;
    }

    for (int i = tid; i < VROWS * 64; i += VTHR) {
        int r = i >> 6, c = i & 63;
        float2 z = *(const float2*)(g_ze + (size_t)(rbase + r) * DIMC + c * 2);
        __half2 hp(__float2half_rn(z.x), __float2half_rn(z.y));
        zhS[r * APW + c] = *(u32*)&hp;
    }
    CP_WAIT0();
    __syncthreads();

    const int r0 = mbase + g;
    const float mg0 = margS[r0], mg1 = margS[r0 + 8];
    const float mg2 = margS[r0 + 16], mg3 = margS[r0 + 24];

    float dacc[2][4][4];

    for (int q = 0; q < NCHUNK; q++) {
        u32* chD = chB + (u32)(q & 1) * (CHBYTES / 4);

        if (q < NCHUNK - 1) {
            const char* src = (const char*)(g_ch16 + (size_t)(q + 1) * CHN * DIMC);
            const u32 dstBase = chBase + (u32)((q + 1) & 1) * CHBYTES;
            #pragma unroll
            for (int t = 0; t < 8; t++) {
                int i = t * VTHR + tid;
                u32 dst = dstBase + ((u32)(i >> 4) * APW + (u32)(i & 15) * 4) * 4;
                cp16(dst, src + (size_t)i * 16);
            }
            CP_COMMIT();
        }

        #pragma unroll
        for (int mt = 0; mt < 2; mt++)
            #pragma unroll
            for (int nt = 0; nt < 4; nt++) {
                dacc[mt][nt][0] = 0.f; dacc[mt][nt][1] = 0.f;
                dacc[mt][nt][2] = 0.f; dacc[mt][nt][3] = 0.f;
            }

        #pragma unroll
        for (int kt = 0; kt < 8; kt++) {
            const int ka = kt * 8 + tg;
            u32 a[2][4];
            #pragma unroll
            for (int mt = 0; mt < 2; mt++) {
                const int rb = (mbase + mt * 16 + g) * APW;
                a[mt][0] = zhS[rb + ka];
                a[mt][1] = zhS[rb + 8 * APW + ka];
                a[mt][2] = zhS[rb + ka + 4];
                a[mt][3] = zhS[rb + 8 * APW + ka + 4];
            }
            #pragma unroll
            for (int nt = 0; nt < 4; nt++) {
                const int w = (nq + nt * 8 + g) * APW + ka;
                const u32 b0 = chD[w], b1 = chD[w + 4];
                mma16816(dacc[0][nt], a[0][0], a[0][1], a[0][2], a[0][3], b0, b1);
                mma16816(dacc[1][nt], a[1][0], a[1][1], a[1][2], a[1][3], b0, b1);
            }
        }

        u32 mn0 = ~0u, mn1 = ~0u, mn2 = ~0u, mn3 = ~0u;
        #pragma unroll
        for (int mt = 0; mt < 2; mt++)
            #pragma unroll
            for (int nt = 0; nt < 4; nt++) {
                const int jb = q * CHN + nq + nt * 8 + 2 * tg;
                const float cn0 = __ldg(g_cnorm + jb);
                const float cn1 = __ldg(g_cnorm + jb + 1);
                float* d = dacc[mt][nt];
                float s0 = fmaf(d[0], -2.0f * DOTSCALE, cn0);
                float s1 = fmaf(d[1], -2.0f * DOTSCALE, cn1);
                float s2 = fmaf(d[2], -2.0f * DOTSCALE, cn0);
                float s3 = fmaf(d[3], -2.0f * DOTSCALE, cn1);
                d[0] = s0; d[1] = s1; d[2] = s2; d[3] = s3;
                u32 ma = min(fmap(s0), fmap(s1));
                u32 mb = min(fmap(s2), fmap(s3));
                if (mt == 0) { mn0 = min(mn0, ma); mn1 = min(mn1, mb); }
                else         { mn2 = min(mn2, ma); mn3 = min(mn3, mb); }
            }
        atomicMin(&bestU[r0],      mn0);
        atomicMin(&bestU[r0 + 8],  mn1);
        atomicMin(&bestU[r0 + 16], mn2);
        atomicMin(&bestU[r0 + 24], mn3);
        __syncthreads();

        const float t0 = finv(bestU[r0])      + mg0;
        const float t1 = finv(bestU[r0 + 8])  + mg1;
        const float t2 = finv(bestU[r0 + 16]) + mg2;
        const float t3 = finv(bestU[r0 + 24]) + mg3;

        #pragma unroll
        for (int mt = 0; mt < 2; mt++) {
            const int rA = r0 + mt * 16, rB = rA + 8;
            const float tA = mt ? t2 : t0;
            const float tB = mt ? t3 : t1;
            #pragma unroll
            for (int nt = 0; nt < 4; nt++) {
                const int jb = q * CHN + nq + nt * 8 + 2 * tg;
                const float* d = dacc[mt][nt];
                if (d[0] <= tA) {
                    u32 p = atomicAdd(&cntS[rA], 1u);
                    if (p < CAND_MAX) candS[rA * CAND_MAX + p] = (u32)jb;
                }
                if (d[1] <= tA) {
                    u32 p = atomicAdd(&cntS[rA], 1u);
                    if (p < CAND_MAX) candS[rA * CAND_MAX + p] = (u32)(jb + 1);
                }
                if (d[2] <= tB) {
                    u32 p = atomicAdd(&cntS[rB], 1u);
                    if (p < CAND_MAX) candS[rB * CAND_MAX + p] = (u32)jb;
                }
                if (d[3] <= tB) {
                    u32 p = atomicAdd(&cntS[rB], 1u);
                    if (p < CAND_MAX) candS[rB * CAND_MAX + p] = (u32)(jb + 1);
                }
            }
        }

        if (q < NCHUNK - 1) CP_WAIT0();
        __syncthreads();
    }

    {
        const int rr = tid >> 2, c4 = tid & 3;
        const float zn = g_znorm[rbase + rr];
        const float* zp = g_ze + (size_t)(rbase + rr) * DIMC;
        int cnt = (int)cntS[rr];
        if (cnt <= CAND_MAX) {
            for (int c = c4; c < cnt; c += 4) {
                int j = (int)candS[rr * CAND_MAX + c];
                const float* cp = cb + (size_t)j * DIMC;
                float dot = 0.f;
                #pragma unroll 8
                for (int d = 0; d < DIMC; d++) dot = fmaf(zp[d], cp[d], dot);
                float dvv = (zn - 2.0f * dot) + __ldg(g_cnorm + j);
                u64 key = ((u64)fmap(dvv) << 32) | (u32)j;
                atomicMin(&finalS[rr], key);
            }
        } else {
            for (int j = c4; j < KC; j += 4) {
                const float* cp = cb + (size_t)j * DIMC;
                float dot = 0.f;
                #pragma unroll 8
                for (int d = 0; d < DIMC; d++) dot = fmaf(zp[d], cp[d], dot);
                float dvv = (zn - 2.0f * dot) + __ldg(g_cnorm + j);
                u64 key = ((u64)fmap(dvv) << 32) | (u32)j;
                atomicMin(&finalS[rr], key);
            }
        }
    }
    __syncthreads();

    if (tid < VROWS) {
        int idx = (int)(finalS[tid] & 0xFFFFFFFFull);
        g_idx[rbase + tid] = idx;
        float* out_id = out + (size_t)nrows * XD + (size_t)nrows * DIMC * 2;
        out_id[rbase + tid] = (float)idx;
    }
}

// ---------------- decoder (fp16 3-term; 64 rows, 256 thr, 2 CTAs/SM) ---------
// smem: xh @0 (17408) | xl @17408 (17408) | wh @34816 (34816) | wl @69632 (34816)
// h2S fp32 [128 dim][68 row pitch] aliases @34816 (34816B) ; end 104448
#define DEC_SMEM 104448

__global__ void __launch_bounds__(DTHR, 2) dec_kernel(
    const float* __restrict__ state, const float* __restrict__ cb,
    const float* __restrict__ db1, const float* __restrict__ db2,
    const float* __restrict__ dw3, const float* __restrict__ db3,
    float* __restrict__ out, int nrows)
{
    extern __shared__ char smc[];
    u32* xhS = (u32*)(smc);
    u32* xlS = (u32*)(smc + 17408);
    u32* whS = (u32*)(smc + 34816);
    u32* wlS = (u32*)(smc + 69632);
    float* h2S = (float*)(smc + 34816);   // alias over whS (34816B)

    const int tid  = threadIdx.x;
    const int wid  = tid >> 5, lane = tid & 31;
    const int g    = lane >> 2, tg = lane & 3;
    const int rbase = blockIdx.x * DROWS;

    // 8 warps = 2 M-groups (32 rows) x 4 N-quarters (32 cols)
    const int mbase = (wid >> 2) * 32;
    const int nq    = (wid & 3) * 32;

    const size_t B = (size_t)nrows;
    float* out_xt = out;
    float* out_zq = out + B * XD + B * (size_t)DIMC;

    float dacc[2][4][4];
    #pragma unroll
    for (int mt = 0; mt < 2; mt++)
        #pragma unroll
        for (int nt = 0; nt < 4; nt++) {
            dacc[mt][nt][0] = 0.f; dacc[mt][nt][1] = 0.f;
            dacc[mt][nt][2] = 0.f; dacc[mt][nt][3] = 0.f;
        }

    // ---- GEMM1: K=384 in 3 chunks of 128 ----
    for (int ch = 0; ch < 3; ch++) {
        if (ch < 2) {
            for (int i = tid; i < DROWS * 64; i += DTHR) {
                int r = i >> 6, cw = i & 63;
                float2 v = *(const float2*)(state + (size_t)(rbase + r) * SDIM + ch * 128 + 2 * cw);
                float v0 = v.x * 16.0f, v1 = v.y * 16.0f;
                __half h0 = __float2half_rn(v0), h1 = __float2half_rn(v1);
                __half l0 = __float2half_rn(v0 - __half2float(h0));
                __half l1 = __float2half_rn(v1 - __half2float(h1));
                __half2 hp(h0, h1), lp(l0, l1);
                xhS[r * APW + cw] = *(u32*)&hp;
                xlS[r * APW + cw] = *(u32*)&lp;
            }
        } else {
            for (int i = tid; i < DROWS * 64; i += DTHR) {
                int r = i >> 6, cw = i & 63;
                int d = 2 * cw;
                float2 z = *(const float2*)(g_ze + (size_t)(rbase + r) * DIMC + d);
                int idx = g_idx[rbase + r];
                float2 q = *(const float2*)(cb + (size_t)idx * DIMC + d);
                *(float2*)(out_zq + (size_t)(rbase + r) * DIMC + d) = q;
                float v0 = (z.x + (q.x - z.x)) * 16.0f;
                float v1 = (z.y + (q.y - z.y)) * 16.0f;
                __half h0 = __float2half_rn(v0), h1 = __float2half_rn(v1);
                __half l0 = __float2half_rn(v0 - __half2float(h0));
                __half l1 = __float2half_rn(v1 - __half2float(h1));
                __half2 hp(h0, h1), lp(l0, l1);
                xhS[r * APW + cw] = *(u32*)&hp;
                xlS[r * APW + cw] = *(u32*)&lp;
            }
        }
        {
            const u32* srcH = (const u32*)g_w1h;
            const u32* srcL = (const u32*)g_w1l;
            for (int i = tid; i < 128 * 64; i += DTHR) {
                int n = i >> 6, cw = i & 63;
                int woff = n * 192 + ch * 64 + cw;
                whS[n * APW + cw] = srcH[woff];
                wlS[n * APW + cw] = srcL[woff];
            }
        }
        __syncthreads();

        #pragma unroll
        for (int kt = 0; kt < 8; kt++) {
            const int ka = kt * 8 + tg;
            u32 ah[2][4], al[2][4];
            #pragma unroll
            for (int mt = 0; mt < 2; mt++) {
                const int rb = (mbase + mt * 16 + g) * APW;
                ah[mt][0] = xhS[rb + ka];
                ah[mt][1] = xhS[rb + 8 * APW + ka];
                ah[mt][2] = xhS[rb + ka + 4];
                ah[mt][3] = xhS[rb + 8 * APW + ka + 4];
                al[mt][0] = xlS[rb + ka];
                al[mt][1] = xlS[rb + 8 * APW + ka];
                al[mt][2] = xlS[rb + ka + 4];
                al[mt][3] = xlS[rb + 8 * APW + ka + 4];
            }
            #pragma unroll
            for (int nt = 0; nt < 4; nt++) {
                const int w = (nq + nt * 8 + g) * APW + ka;
                const u32 bh0 = whS[w], bh1 = whS[w + 4];
                const u32 bl0 = wlS[w], bl1 = wlS[w + 4];
                #pragma unroll
                for (int mt = 0; mt < 2; mt++) {
                    mma16816(dacc[mt][nt], ah[mt][0], ah[mt][1], ah[mt][2], ah[mt][3], bh0, bh1);
                    mma16816(dacc[mt][nt], al[mt][0], al[mt][1], al[mt][2], al[mt][3], bh0, bh1);
                    mma16816(dacc[mt][nt], ah[mt][0], ah[mt][1], ah[mt][2], ah[mt][3], bl0, bl1);
                }
            }
        }
        __syncthreads();
    }

    // ---- GEMM1 epilogue: h1 = relu(acc/1024 + b1); restage (x16 split) ----
    #pragma unroll
    for (int mt = 0; mt < 2; mt++) {
        const int rA = mbase + mt * 16 + g, rB = rA + 8;
        #pragma unroll
        for (int nt = 0; nt < 4; nt++) {
            const int jb = nq + nt * 8 + 2 * tg;
            const float b0v = __ldg(db1 + jb), b1v = __ldg(db1 + jb + 1);
            float* d = dacc[mt][nt];
            float s0 = fmaxf(fmaf(d[0], DOTSCALE, b0v), 0.f) * 16.0f;
            float s1 = fmaxf(fmaf(d[1], DOTSCALE, b1v), 0.f) * 16.0f;
            float s2 = fmaxf(fmaf(d[2], DOTSCALE, b0v), 0.f) * 16.0f;
            float s3 = fmaxf(fmaf(d[3], DOTSCALE, b1v), 0.f) * 16.0f;
            const int w = (nq >> 1) + nt * 4 + tg;
            __half h0 = __float2half_rn(s0), h1 = __float2half_rn(s1);
            __half l0 = __float2half_rn(s0 - __half2float(h0));
            __half l1 = __float2half_rn(s1 - __half2float(h1));
            __half2 hpA(h0, h1), lpA(l0, l1);
            xhS[rA * APW + w] = *(u32*)&hpA;
            xlS[rA * APW + w] = *(u32*)&lpA;
            __half h2 = __float2half_rn(s2), h3 = __float2half_rn(s3);
            __half l2 = __float2half_rn(s2 - __half2float(h2));
            __half l3 = __float2half_rn(s3 - __half2float(h3));
            __half2 hpB(h2, h3), lpB(l2, l3);
            xhS[rB * APW + w] = *(u32*)&hpB;
            xlS[rB * APW + w] = *(u32*)&lpB;
        }
    }
    {
        const u32* srcH = (const u32*)g_w2h;
        const u32* srcL = (const u32*)g_w2l;
        for (int i = tid; i < 128 * 64; i += DTHR) {
            int n = i >> 6, cw = i & 63;
            whS[n * APW + cw] = srcH[n * 64 + cw];
            wlS[n * APW + cw] = srcL[n * 64 + cw];
        }
    }
    __syncthreads();

    // ---- GEMM2: K=128 ----
    #pragma unroll
    for (int mt = 0; mt < 2; mt++)
        #pragma unroll
        for (int nt = 0; nt < 4; nt++) {
            dacc[mt][nt][0] = 0.f; dacc[mt][nt][1] = 0.f;
            dacc[mt][nt][2] = 0.f; dacc[mt][nt][3] = 0.f;
        }
    #pragma unroll
    for (int kt = 0; kt < 8; kt++) {
        const int ka = kt * 8 + tg;
        u32 ah[2][4], al[2][4];
        #pragma unroll
        for (int mt = 0; mt < 2; mt++) {
            const int rb = (mbase + mt * 16 + g) * APW;
            ah[mt][0] = xhS[rb + ka];
            ah[mt][1] = xhS[rb + 8 * APW + ka];
            ah[mt][2] = xhS[rb + ka + 4];
            ah[mt][3] = xhS[rb + 8 * APW + ka + 4];
            al[mt][0] = xlS[rb + ka];
            al[mt][1] = xlS[rb + 8 * APW + ka];
            al[mt][2] = xlS[rb + ka + 4];
            al[mt][3] = xlS[rb + 8 * APW + ka + 4];
        }
        #pragma unroll
        for (int nt = 0; nt < 4; nt++) {
            const int w = (nq + nt * 8 + g) * APW + ka;
            const u32 bh0 = whS[w], bh1 = whS[w + 4];
            const u32 bl0 = wlS[w], bl1 = wlS[w + 4];
            #pragma unroll
            for (int mt = 0; mt < 2; mt++) {
                mma16816(dacc[mt][nt], ah[mt][0], ah[mt][1], ah[mt][2], ah[mt][3], bh0, bh1);
                mma16816(dacc[mt][nt], al[mt][0], al[mt][1], al[mt][2], al[mt][3], bh0, bh1);
                mma16816(dacc[mt][nt], ah[mt][0], ah[mt][1], ah[mt][2], ah[mt][3], bl0, bl1);
            }
        }
    }
    __syncthreads();   // wh/wl reads done before h2 alias-write

    // ---- GEMM2 epilogue: h2 fp32 -> h2S [dim][68 row pitch] ----
    #pragma unroll
    for (int mt = 0; mt < 2; mt++) {
        const int rA = mbase + mt * 16 + g, rB = rA + 8;
        #pragma unroll
        for (int nt = 0; nt < 4; nt++) {
            const int jb = nq + nt * 8 + 2 * tg;
            const float b0v = __ldg(db2 + jb), b1v = __ldg(db2 + jb + 1);
            float* d = dacc[mt][nt];
            h2S[jb * APW + rA]       = fmaxf(fmaf(d[0], DOTSCALE, b0v), 0.f);
            h2S[(jb + 1) * APW + rA] = fmaxf(fmaf(d[1], DOTSCALE, b1v), 0.f);
            h2S[jb * APW + rB]       = fmaxf(fmaf(d[2], DOTSCALE, b0v), 0.f);
            h2S[(jb + 1) * APW + rB] = fmaxf(fmaf(d[3], DOTSCALE, b1v), 0.f);
        }
    }
    __syncthreads();

    // ---- final layer: fp32 scalar, 64 rows x 8 cols ----
    {
        int r = tid & 63;
        int c = (tid >> 6) * 2;
        float a0 = 0.f, a1 = 0.f;
        #pragma unroll 4
        for (int d = 0; d < DIMC; d++) {
            float h = h2S[d * APW + r];
            a0 = fmaf(h, dw3[d * XD + c],     a0);
            a1 = fmaf(h, dw3[d * XD + c + 1], a1);
        }
        out_xt[(size_t)(rbase + r) * XD + c]     = a0 + db3[c];
        out_xt[(size_t)(rbase + r) * XD + c + 1] = a1 + db3[c + 1];
    }
}

// ---------------- launch ----------------
extern "C" void kernel_launch(void* const* d_in, const int* in_sizes, int n_in,
                              void* d_out, int out_size) {
    const float* state = (const float*)d_in[0];
    const float* x     = (const float*)d_in[1];
    const float* cb    = (const float*)d_in[2];
    const float* ew1   = (const float*)d_in[3];
    const float* eb1   = (const float*)d_in[4];
    const float* ew2   = (const float*)d_in[5];
    const float* eb2   = (const float*)d_in[6];
    const float* ew3   = (const float*)d_in[7];
    const float* eb3   = (const float*)d_in[8];
    const float* dw1   = (const float*)d_in[9];
    const float* db1   = (const float*)d_in[10];
    const float* dw2   = (const float*)d_in[11];
    const float* db2   = (const float*)d_in[12];
    const float* dw3   = (const float*)d_in[13];
    const float* db3   = (const float*)d_in[14];

    const int nrows = in_sizes[0] / SDIM;   // 262144

    size_t smemA = (size_t)(136 + 128) * PITCH * sizeof(float);   // 71808
    static bool attrs_set = false;
    if (!attrs_set) {
        cudaFuncSetAttribute((const void*)enc_kernel, cudaFuncAttributeMaxDynamicSharedMemorySize, (int)smemA);
        cudaFuncSetAttribute((const void*)vq_kernel,  cudaFuncAttributeMaxDynamicSharedMemorySize, VQ_SMEM);
        cudaFuncSetAttribute((const void*)dec_kernel, cudaFuncAttributeMaxDynamicSharedMemorySize, DEC_SMEM);
        attrs_set = true;
    }

    vq_prep<<<KC, DIMC>>>(cb);
    dec_prep<<<(128 * 384 + 128 * 128 + 255) / 256, 256>>>(dw1, dw2);
    enc_kernel<<<nrows / ROWS, NTHR, smemA>>>(state, x, ew1, eb1, ew2, eb2, ew3, eb3,
                                              (float*)d_out, nrows);
    vq_kernel<<<nrows / VROWS, VTHR, VQ_SMEM>>>(cb, (float*)d_out, nrows);
    dec_kernel<<<nrows / DROWS, DTHR, DEC_SMEM>>>(state, cb, db1, db2, dw3, db3,
                                                  (float*)d_out, nrows);
}

// round 17
// speedup vs baseline: 3.0729x; 1.0203x over previous
#include <cuda_runtime.h>
#include <cuda_fp16.h>
#include <cstdint>

typedef unsigned long long u64;
typedef unsigned int u32;

#define PITCH   68
#define ROWS    64
#define NTHR    256
#define DIMC    128
#define KC      1024
#define SDIM    256
#define XD      8
#define BTOT    262144

#define NCHUNK  8
#define CHN     128
#define CAND_MAX 32
#define APW     68
#define DOTSCALE 0.0009765625f   // 2^-10 exact

#define DROWS   64
#define DTHR    256

// ---------------- scratch globals ----------------
__device__ float   g_cnorm[KC];
__device__ __half  g_ch16[KC * DIMC];       // fp16(codebook * 1024)
__device__ float   g_ze[(size_t)BTOT * DIMC];
__device__ int     g_idx[BTOT];
__device__ __half  g_w1h[128 * 384];        // dec w1^T * 64 (hi/lo)
__device__ __half  g_w1l[128 * 384];
__device__ __half  g_w2h[128 * 128];
__device__ __half  g_w2l[128 * 128];

// ---------------- prep ----------------
__global__ void vq_prep(const float* __restrict__ cb) {
    int j = blockIdx.x;
    int d = threadIdx.x;
    float v = cb[j * DIMC + d];
    g_ch16[j * DIMC + d] = __float2half_rn(v * 1024.0f);
    __shared__ float red[DIMC];
    red[d] = v * v;
    __syncthreads();
    #pragma unroll
    for (int s = 64; s > 0; s >>= 1) {
        if (d < s) red[d] += red[d + s];
        __syncthreads();
    }
    if (d == 0) g_cnorm[j] = red[0];
}

__global__ void dec_prep(const float* __restrict__ dw1, const float* __restrict__ dw2) {
    int i = blockIdx.x * 256 + threadIdx.x;
    if (i < 128 * 384) {
        int n = i / 384, k = i % 384;
        float v = dw1[k * 128 + n] * 64.0f;
        __half h = __float2half_rn(v);
        g_w1h[i] = h;
        g_w1l[i] = __float2half_rn(v - __half2float(h));
    } else if (i < 128 * 384 + 128 * 128) {
        int j = i - 128 * 384;
        int n = j / 128, k = j % 128;
        float v = dw2[k * 128 + n] * 64.0f;
        __half h = __float2half_rn(v);
        g_w2h[j] = h;
        g_w2l[j] = __float2half_rn(v - __half2float(h));
    }
}

// ---------------- packed f32x2 helpers ----------------
__device__ __forceinline__ u64 dup2(float w) {
    u64 r; unsigned u = __float_as_uint(w);
    asm("mov.b64 %0, {%1, %1};" : "=l"(r) : "r"(u));
    return r;
}
__device__ __forceinline__ void ffma2(u64& d, u64 a, u64 b) {
    asm("fma.rn.f32x2 %0, %1, %2, %0;" : "+l"(d) : "l"(a), "l"(b));
}
__device__ __forceinline__ float2 unpk(u64 v) {
    unsigned lo, hi;
    asm("mov.b64 {%0, %1}, %2;" : "=r"(lo), "=r"(hi) : "l"(v));
    return make_float2(__uint_as_float(lo), __uint_as_float(hi));
}

// ---------------- fp32 gemm (accumulate + store split) ----------------
__device__ __forceinline__ void gemm_accum(
    const float* __restrict__ inS, int Kdim,
    const float* __restrict__ W, u64 (&acc)[4][4], int warp, int lane)
{
    const int r0 = warp * 8;
    const int c0 = lane * 4;
    #pragma unroll 4
    for (int k = 0; k < Kdim; k++) {
        const ulonglong2 aA = *(const ulonglong2*)(inS + k * PITCH + r0);
        const ulonglong2 aB = *(const ulonglong2*)(inS + k * PITCH + r0 + 4);
        const float4 w = *(const float4*)(W + (size_t)k * DIMC + c0);
        const u64 wd[4] = {dup2(w.x), dup2(w.y), dup2(w.z), dup2(w.w)};
        const u64 av[4] = {aA.x, aA.y, aB.x, aB.y};
        #pragma unroll
        for (int i = 0; i < 4; i++) {
            ffma2(acc[i][0], av[i], wd[0]);
            ffma2(acc[i][1], av[i], wd[1]);
            ffma2(acc[i][2], av[i], wd[2]);
            ffma2(acc[i][3], av[i], wd[3]);
        }
    }
}
__device__ __forceinline__ void gemm_store(
    u64 (&acc)[4][4], const float* __restrict__ bias,
    float* __restrict__ outS, bool relu, int warp, int lane)
{
    const int r0 = warp * 8;
    const int c0 = lane * 4;
    const float4 b = *(const float4*)(bias + c0);
    const float bv[4] = {b.x, b.y, b.z, b.w};
    #pragma unroll
    for (int j = 0; j < 4; j++) {
        float o[8];
        #pragma unroll
        for (int i = 0; i < 4; i++) {
            float2 p = unpk(acc[i][j]);
            float v0 = p.x + bv[j];
            float v1 = p.y + bv[j];
            o[2 * i]     = relu ? fmaxf(v0, 0.f) : v0;
            o[2 * i + 1] = relu ? fmaxf(v1, 0.f) : v1;
        }
        *(float4*)(outS + (c0 + j) * PITCH + r0)     = make_float4(o[0], o[1], o[2], o[3]);
        *(float4*)(outS + (c0 + j) * PITCH + r0 + 4) = make_float4(o[4], o[5], o[6], o[7]);
    }
}
#define ACC_ZERO(acc) do { _Pragma("unroll") \
    for (int _i = 0; _i < 4; _i++) { acc[_i][0]=0; acc[_i][1]=0; acc[_i][2]=0; acc[_i][3]=0; } } while (0)

// ---------------- fp16 mma helpers ----------------
__device__ __forceinline__ void mma16816(float* d, u32 a0, u32 a1, u32 a2, u32 a3,
                                         u32 b0, u32 b1) {
    asm volatile(
        "mma.sync.aligned.m16n8k16.row.col.f32.f16.f16.f32 "
        "{%0,%1,%2,%3}, {%4,%5,%6,%7}, {%8,%9}, {%0,%1,%2,%3};"
        : "+f"(d[0]), "+f"(d[1]), "+f"(d[2]), "+f"(d[3])
        : "r"(a0), "r"(a1), "r"(a2), "r"(a3), "r"(b0), "r"(b1));
}
__device__ __forceinline__ u32 fmap(float f) {
    u32 u = __float_as_uint(f);
    return (u & 0x80000000u) ? ~u : (u | 0x80000000u);
}
__device__ __forceinline__ float finv(u32 m) {
    u32 u = (m & 0x80000000u) ? (m ^ 0x80000000u) : ~m;
    return __uint_as_float(u);
}

// ---------------- fused encoder + VQ (64 rows, 256 thr, 2 CTAs/SM) ----------
// smem layout (bytes):
//   enc phase:  X  [136][68] f32 @ 0       (36992)
//               hA [128][68] f32 @ 61952   (34816)   -- z_e, persists
//   vq phase:   finalS u64[64] @0 (512) | margS f32[64] @512 | bestU @768
//               cntS @1024 | candS u32[64*32] @1280 (8192) -> 9472
//               znormS f32[64] @9472 (256) -> 9728
//               zhS u32[64][68] @9728 (17408) -> 27136
//               chS u32[128][68] @27136 (34816) -> 61952
//   total 96768 -> 2 CTAs/SM
#define F_SMEM 96768

__global__ void __launch_bounds__(NTHR, 2) fused_kernel(
    const float* __restrict__ state, const float* __restrict__ x,
    const float* __restrict__ ew1, const float* __restrict__ eb1,
    const float* __restrict__ ew2, const float* __restrict__ eb2,
    const float* __restrict__ ew3, const float* __restrict__ eb3,
    const float* __restrict__ cb,
    float* __restrict__ out, int nrows)
{
    extern __shared__ char smc[];
    float* X  = (float*)smc;                 // [136][PITCH]
    float* hA = (float*)(smc + 61952);       // [128][PITCH]  z_e
    u64*   finalS = (u64*)(smc);
    float* margS  = (float*)(smc + 512);
    u32*   bestU  = (u32*)(smc + 768);
    u32*   cntS   = (u32*)(smc + 1024);
    u32*   candS  = (u32*)(smc + 1280);
    float* znormS = (float*)(smc + 9472);
    u32*   zhS    = (u32*)(smc + 9728);
    u32*   chS    = (u32*)(smc + 27136);

    const int tid  = threadIdx.x;
    const int warp = tid >> 5, lane = tid & 31;
    const int rbase = blockIdx.x * ROWS;
    const size_t B = (size_t)nrows;

    // ================= encoder (fp32, R16-identical math) =================
    {
        u64 acc[4][4];
        ACC_ZERO(acc);

        for (int e = tid; e < ROWS * 128; e += NTHR) {
            int r = e >> 7, k = e & 127;
            X[k * PITCH + r] = state[(size_t)(rbase + r) * SDIM + k];
        }
        __syncthreads();
        gemm_accum(X, 128, ew1, acc, warp, lane);
        __syncthreads();

        for (int e = tid; e < ROWS * 128; e += NTHR) {
            int r = e >> 7, k = e & 127;
            X[k * PITCH + r] = state[(size_t)(rbase + r) * SDIM + 128 + k];
        }
        for (int e = tid; e < ROWS * XD; e += NTHR) {
            int r = e >> 3, k = e & 7;
            X[(128 + k) * PITCH + r] = x[(size_t)(rbase + r) * XD + k];
        }
        __syncthreads();
        gemm_accum(X, 136, ew1 + (size_t)128 * DIMC, acc, warp, lane);
        gemm_store(acc, eb1, hA, true, warp, lane);
        __syncthreads();

        ACC_ZERO(acc);
        gemm_accum(hA, DIMC, ew2, acc, warp, lane);
        gemm_store(acc, eb2, X, true, warp, lane);
        __syncthreads();

        ACC_ZERO(acc);
        gemm_accum(X, DIMC, ew3, acc, warp, lane);
        __syncthreads();                       // all X reads done before ctrl aliasing
        gemm_store(acc, eb3, hA, false, warp, lane);   // z_e -> hA
        __syncthreads();
    }

    // ================= staging for VQ (ctrl region aliases X) ==============
    if (tid < ROWS) {
        float s = 0.f, a = 0.f;
        #pragma unroll 4
        for (int d = 0; d < DIMC; d++) {
            float z = hA[d * PITCH + tid];
            s = fmaf(z, z, s);
            a += fabsf(z);
        }
        znormS[tid] = s;
        margS[tid]  = a * 4.0e-6f + 4.0e-6f;
        bestU[tid]  = 0xFFFFFFFFu;
        finalS[tid] = ~0ull;
        cntS[tid]   = 0u;
    }

    // z_e outputs (dec needs g_ze)
    float* out_ze = out + B * XD;
    for (int e = tid; e < ROWS * DIMC; e += NTHR) {
        int r = e >> 7, d = e & 127;
        float z = hA[d * PITCH + r];
        out_ze[(size_t)(rbase + r) * DIMC + d] = z;
        g_ze[(size_t)(rbase + r) * DIMC + d]   = z;
    }

    // zh tile from smem z_e
    for (int i = tid; i < ROWS * 64; i += NTHR) {
        int r = i >> 6, c = i & 63;
        float z0 = hA[(2 * c)     * PITCH + r];
        float z1 = hA[(2 * c + 1) * PITCH + r];
        __half2 hp(__float2half_rn(z0), __float2half_rn(z1));
        zhS[r * APW + c] = *(u32*)&hp;
    }

    // stage codebook chunk 0
    {
        const uint4* src = (const uint4*)(g_ch16);
        #pragma unroll
        for (int t = 0; t < 8; t++) {
            int i = t * NTHR + tid;
            uint4 v = src[i];
            *(uint4*)(chS + (i >> 4) * APW + (i & 15) * 4) = v;
        }
    }
    __syncthreads();

    // ================= VQ screen (R10-identical) ===========================
    const int g  = lane >> 2, tg = lane & 3;
    const int mbase = (warp >> 2) * 32;
    const int nq    = (warp & 3) * 32;
    const int r0 = mbase + g;
    const float mg0 = margS[r0], mg1 = margS[r0 + 8];
    const float mg2 = margS[r0 + 16], mg3 = margS[r0 + 24];

    float dacc[2][4][4];

    for (int q = 0; q < NCHUNK; q++) {
        #pragma unroll
        for (int mt = 0; mt < 2; mt++)
            #pragma unroll
            for (int nt = 0; nt < 4; nt++) {
                dacc[mt][nt][0] = 0.f; dacc[mt][nt][1] = 0.f;
                dacc[mt][nt][2] = 0.f; dacc[mt][nt][3] = 0.f;
            }

        #pragma unroll
        for (int kt = 0; kt < 8; kt++) {
            const int ka = kt * 8 + tg;
            u32 a[2][4];
            #pragma unroll
            for (int mt = 0; mt < 2; mt++) {
                const int rb = (mbase + mt * 16 + g) * APW;
                a[mt][0] = zhS[rb + ka];
                a[mt][1] = zhS[rb + 8 * APW + ka];
                a[mt][2] = zhS[rb + ka + 4];
                a[mt][3] = zhS[rb + 8 * APW + ka + 4];
            }
            #pragma unroll
            for (int nt = 0; nt < 4; nt++) {
                const int w = (nq + nt * 8 + g) * APW + ka;
                const u32 b0 = chS[w], b1 = chS[w + 4];
                mma16816(dacc[0][nt], a[0][0], a[0][1], a[0][2], a[0][3], b0, b1);
                mma16816(dacc[1][nt], a[1][0], a[1][1], a[1][2], a[1][3], b0, b1);
            }
        }

        u32 mn0 = ~0u, mn1 = ~0u, mn2 = ~0u, mn3 = ~0u;
        #pragma unroll
        for (int mt = 0; mt < 2; mt++)
            #pragma unroll
            for (int nt = 0; nt < 4; nt++) {
                const int jb = q * CHN + nq + nt * 8 + 2 * tg;
                const float cn0 = __ldg(g_cnorm + jb);
                const float cn1 = __ldg(g_cnorm + jb + 1);
                float* d = dacc[mt][nt];
                float s0 = fmaf(d[0], -2.0f * DOTSCALE, cn0);
                float s1 = fmaf(d[1], -2.0f * DOTSCALE, cn1);
                float s2 = fmaf(d[2], -2.0f * DOTSCALE, cn0);
                float s3 = fmaf(d[3], -2.0f * DOTSCALE, cn1);
                d[0] = s0; d[1] = s1; d[2] = s2; d[3] = s3;
                u32 ma = min(fmap(s0), fmap(s1));
                u32 mb = min(fmap(s2), fmap(s3));
                if (mt == 0) { mn0 = min(mn0, ma); mn1 = min(mn1, mb); }
                else         { mn2 = min(mn2, ma); mn3 = min(mn3, mb); }
            }
        atomicMin(&bestU[r0],      mn0);
        atomicMin(&bestU[r0 + 8],  mn1);
        atomicMin(&bestU[r0 + 16], mn2);
        atomicMin(&bestU[r0 + 24], mn3);
        __syncthreads();   // mins global; all chS reads complete

        const float t0 = finv(bestU[r0])      + mg0;
        const float t1 = finv(bestU[r0 + 8])  + mg1;
        const float t2 = finv(bestU[r0 + 16]) + mg2;
        const float t3 = finv(bestU[r0 + 24]) + mg3;

        #pragma unroll
        for (int mt = 0; mt < 2; mt++) {
            const int rA = r0 + mt * 16, rB = rA + 8;
            const float tA = mt ? t2 : t0;
            const float tB = mt ? t3 : t1;
            #pragma unroll
            for (int nt = 0; nt < 4; nt++) {
                const int jb = q * CHN + nq + nt * 8 + 2 * tg;
                const float* d = dacc[mt][nt];
                if (d[0] <= tA) {
                    u32 p = atomicAdd(&cntS[rA], 1u);
                    if (p < CAND_MAX) candS[rA * CAND_MAX + p] = (u32)jb;
                }
                if (d[1] <= tA) {
                    u32 p = atomicAdd(&cntS[rA], 1u);
                    if (p < CAND_MAX) candS[rA * CAND_MAX + p] = (u32)(jb + 1);
                }
                if (d[2] <= tB) {
                    u32 p = atomicAdd(&cntS[rB], 1u);
                    if (p < CAND_MAX) candS[rB * CAND_MAX + p] = (u32)jb;
                }
                if (d[3] <= tB) {
                    u32 p = atomicAdd(&cntS[rB], 1u);
                    if (p < CAND_MAX) candS[rB * CAND_MAX + p] = (u32)(jb + 1);
                }
            }
        }

        // stage next chunk (chS reads finished at the barrier above; candidate
        // pass touches only candS/cntS)
        if (q < NCHUNK - 1) {
            const uint4* src = (const uint4*)(g_ch16 + (size_t)(q + 1) * CHN * DIMC);
            #pragma unroll
            for (int t = 0; t < 8; t++) {
                int i = t * NTHR + tid;
                uint4 v = src[i];
                *(uint4*)(chS + (i >> 4) * APW + (i & 15) * 4) = v;
            }
        }
        __syncthreads();
    }

    // ================= exact fp32 refine (z from smem, same order) =========
    {
        const int rr = tid >> 2, c4 = tid & 3;
        const float zn = znormS[rr];
        int cnt = (int)cntS[rr];
        if (cnt <= CAND_MAX) {
            for (int c = c4; c < cnt; c += 4) {
                int j = (int)candS[rr * CAND_MAX + c];
                const float* cp = cb + (size_t)j * DIMC;
                float dot = 0.f;
                #pragma unroll 8
                for (int d = 0; d < DIMC; d++) dot = fmaf(hA[d * PITCH + rr], cp[d], dot);
                float dvv = (zn - 2.0f * dot) + __ldg(g_cnorm + j);
                u64 key = ((u64)fmap(dvv) << 32) | (u32)j;
                atomicMin(&finalS[rr], key);
            }
        } else {
            for (int j = c4; j < KC; j += 4) {
                const float* cp = cb + (size_t)j * DIMC;
                float dot = 0.f;
                #pragma unroll 8
                for (int d = 0; d < DIMC; d++) dot = fmaf(hA[d * PITCH + rr], cp[d], dot);
                float dvv = (zn - 2.0f * dot) + __ldg(g_cnorm + j);
                u64 key = ((u64)fmap(dvv) << 32) | (u32)j;
                atomicMin(&finalS[rr], key);
            }
        }
    }
    __syncthreads();

    if (tid < ROWS) {
        int idx = (int)(finalS[tid] & 0xFFFFFFFFull);
        g_idx[rbase + tid] = idx;
        float* out_id = out + B * XD + B * (size_t)DIMC * 2;
        out_id[rbase + tid] = (float)idx;
    }
}

// ---------------- decoder (R16: fp16 3-term; 64 rows, 2 CTAs/SM) ------------
#define DEC_SMEM 104448

__global__ void __launch_bounds__(DTHR, 2) dec_kernel(
    const float* __restrict__ state, const float* __restrict__ cb,
    const float* __restrict__ db1, const float* __restrict__ db2,
    const float* __restrict__ dw3, const float* __restrict__ db3,
    float* __restrict__ out, int nrows)
{
    extern __shared__ char smc[];
    u32* xhS = (u32*)(smc);
    u32* xlS = (u32*)(smc + 17408);
    u32* whS = (u32*)(smc + 34816);
    u32* wlS = (u32*)(smc + 69632);
    float* h2S = (float*)(smc + 34816);   // alias over whS

    const int tid  = threadIdx.x;
    const int wid  = tid >> 5, lane = tid & 31;
    const int g    = lane >> 2, tg = lane & 3;
    const int rbase = blockIdx.x * DROWS;

    const int mbase = (wid >> 2) * 32;
    const int nq    = (wid & 3) * 32;

    const size_t B = (size_t)nrows;
    float* out_xt = out;
    float* out_zq = out + B * XD + B * (size_t)DIMC;

    float dacc[2][4][4];
    #pragma unroll
    for (int mt = 0; mt < 2; mt++)
        #pragma unroll
        for (int nt = 0; nt < 4; nt++) {
            dacc[mt][nt][0] = 0.f; dacc[mt][nt][1] = 0.f;
            dacc[mt][nt][2] = 0.f; dacc[mt][nt][3] = 0.f;
        }

    for (int ch = 0; ch < 3; ch++) {
        if (ch < 2) {
            for (int i = tid; i < DROWS * 64; i += DTHR) {
                int r = i >> 6, cw = i & 63;
                float2 v = *(const float2*)(state + (size_t)(rbase + r) * SDIM + ch * 128 + 2 * cw);
                float v0 = v.x * 16.0f, v1 = v.y * 16.0f;
                __half h0 = __float2half_rn(v0), h1 = __float2half_rn(v1);
                __half l0 = __float2half_rn(v0 - __half2float(h0));
                __half l1 = __float2half_rn(v1 - __half2float(h1));
                __half2 hp(h0, h1), lp(l0, l1);
                xhS[r * APW + cw] = *(u32*)&hp;
                xlS[r * APW + cw] = *(u32*)&lp;
            }
        } else {
            for (int i = tid; i < DROWS * 64; i += DTHR) {
                int r = i >> 6, cw = i & 63;
                int d = 2 * cw;
                float2 z = *(const float2*)(g_ze + (size_t)(rbase + r) * DIMC + d);
                int idx = g_idx[rbase + r];
                float2 q = *(const float2*)(cb + (size_t)idx * DIMC + d);
                *(float2*)(out_zq + (size_t)(rbase + r) * DIMC + d) = q;
                float v0 = (z.x + (q.x - z.x)) * 16.0f;
                float v1 = (z.y + (q.y - z.y)) * 16.0f;
                __half h0 = __float2half_rn(v0), h1 = __float2half_rn(v1);
                __half l0 = __float2half_rn(v0 - __half2float(h0));
                __half l1 = __float2half_rn(v1 - __half2float(h1));
                __half2 hp(h0, h1), lp(l0, l1);
                xhS[r * APW + cw] = *(u32*)&hp;
                xlS[r * APW + cw] = *(u32*)&lp;
            }
        }
        {
            const u32* srcH = (const u32*)g_w1h;
            const u32* srcL = (const u32*)g_w1l;
            for (int i = tid; i < 128 * 64; i += DTHR) {
                int n = i >> 6, cw = i & 63;
                int woff = n * 192 + ch * 64 + cw;
                whS[n * APW + cw] = srcH[woff];
                wlS[n * APW + cw] = srcL[woff];
            }
        }
        __syncthreads();

        #pragma unroll
        for (int kt = 0; kt < 8; kt++) {
            const int ka = kt * 8 + tg;
            u32 ah[2][4], al[2][4];
            #pragma unroll
            for (int mt = 0; mt < 2; mt++) {
                const int rb = (mbase + mt * 16 + g) * APW;
                ah[mt][0] = xhS[rb + ka];
                ah[mt][1] = xhS[rb + 8 * APW + ka];
                ah[mt][2] = xhS[rb + ka + 4];
                ah[mt][3] = xhS[rb + 8 * APW + ka + 4];
                al[mt][0] = xlS[rb + ka];
                al[mt][1] = xlS[rb + 8 * APW + ka];
                al[mt][2] = xlS[rb + ka + 4];
                al[mt][3] = xlS[rb + 8 * APW + ka + 4];
            }
            #pragma unroll
            for (int nt = 0; nt < 4; nt++) {
                const int w = (nq + nt * 8 + g) * APW + ka;
                const u32 bh0 = whS[w], bh1 = whS[w + 4];
                const u32 bl0 = wlS[w], bl1 = wlS[w + 4];
                #pragma unroll
                for (int mt = 0; mt < 2; mt++) {
                    mma16816(dacc[mt][nt], ah[mt][0], ah[mt][1], ah[mt][2], ah[mt][3], bh0, bh1);
                    mma16816(dacc[mt][nt], al[mt][0], al[mt][1], al[mt][2], al[mt][3], bh0, bh1);
                    mma16816(dacc[mt][nt], ah[mt][0], ah[mt][1], ah[mt][2], ah[mt][3], bl0, bl1);
                }
            }
        }
        __syncthreads();
    }

    #pragma unroll
    for (int mt = 0; mt < 2; mt++) {
        const int rA = mbase + mt * 16 + g, rB = rA + 8;
        #pragma unroll
        for (int nt = 0; nt < 4; nt++) {
            const int jb = nq + nt * 8 + 2 * tg;
            const float b0v = __ldg(db1 + jb), b1v = __ldg(db1 + jb + 1);
            float* d = dacc[mt][nt];
            float s0 = fmaxf(fmaf(d[0], DOTSCALE, b0v), 0.f) * 16.0f;
            float s1 = fmaxf(fmaf(d[1], DOTSCALE, b1v), 0.f) * 16.0f;
            float s2 = fmaxf(fmaf(d[2], DOTSCALE, b0v), 0.f) * 16.0f;
            float s3 = fmaxf(fmaf(d[3], DOTSCALE, b1v), 0.f) * 16.0f;
            const int w = (nq >> 1) + nt * 4 + tg;
            __half h0 = __float2half_rn(s0), h1 = __float2half_rn(s1);
            __half l0 = __float2half_rn(s0 - __half2float(h0));
            __half l1 = __float2half_rn(s1 - __half2float(h1));
            __half2 hpA(h0, h1), lpA(l0, l1);
            xhS[rA * APW + w] = *(u32*)&hpA;
            xlS[rA * APW + w] = *(u32*)&lpA;
            __half h2 = __float2half_rn(s2), h3 = __float2half_rn(s3);
            __half l2 = __float2half_rn(s2 - __half2float(h2));
            __half l3 = __float2half_rn(s3 - __half2float(h3));
            __half2 hpB(h2, h3), lpB(l2, l3);
            xhS[rB * APW + w] = *(u32*)&hpB;
            xlS[rB * APW + w] = *(u32*)&lpB;
        }
    }
    {
        const u32* srcH = (const u32*)g_w2h;
        const u32* srcL = (const u32*)g_w2l;
        for (int i = tid; i < 128 * 64; i += DTHR) {
            int n = i >> 6, cw = i & 63;
            whS[n * APW + cw] = srcH[n * 64 + cw];
            wlS[n * APW + cw] = srcL[n * 64 + cw];
        }
    }
    __syncthreads();

    #pragma unroll
    for (int mt = 0; mt < 2; mt++)
        #pragma unroll
        for (int nt = 0; nt < 4; nt++) {
            dacc[mt][nt][0] = 0.f; dacc[mt][nt][1] = 0.f;
            dacc[mt][nt][2] = 0.f; dacc[mt][nt][3] = 0.f;
        }
    #pragma unroll
    for (int kt = 0; kt < 8; kt++) {
        const int ka = kt * 8 + tg;
        u32 ah[2][4], al[2][4];
        #pragma unroll
        for (int mt = 0; mt < 2; mt++) {
            const int rb = (mbase + mt * 16 + g) * APW;
            ah[mt][0] = xhS[rb + ka];
            ah[mt][1] = xhS[rb + 8 * APW + ka];
            ah[mt][2] = xhS[rb + ka + 4];
            ah[mt][3] = xhS[rb + 8 * APW + ka + 4];
            al[mt][0] = xlS[rb + ka];
            al[mt][1] = xlS[rb + 8 * APW + ka];
            al[mt][2] = xlS[rb + ka + 4];
            al[mt][3] = xlS[rb + 8 * APW + ka + 4];
        }
        #pragma unroll
        for (int nt = 0; nt < 4; nt++) {
            const int w = (nq + nt * 8 + g) * APW + ka;
            const u32 bh0 = whS[w], bh1 = whS[w + 4];
            const u32 bl0 = wlS[w], bl1 = wlS[w + 4];
            #pragma unroll
            for (int mt = 0; mt < 2; mt++) {
                mma16816(dacc[mt][nt], ah[mt][0], ah[mt][1], ah[mt][2], ah[mt][3], bh0, bh1);
                mma16816(dacc[mt][nt], al[mt][0], al[mt][1], al[mt][2], al[mt][3], bh0, bh1);
                mma16816(dacc[mt][nt], ah[mt][0], ah[mt][1], ah[mt][2], ah[mt][3], bl0, bl1);
            }
        }
    }
    __syncthreads();

    #pragma unroll
    for (int mt = 0; mt < 2; mt++) {
        const int rA = mbase + mt * 16 + g, rB = rA + 8;
        #pragma unroll
        for (int nt = 0; nt < 4; nt++) {
            const int jb = nq + nt * 8 + 2 * tg;
            const float b0v = __ldg(db2 + jb), b1v = __ldg(db2 + jb + 1);
            float* d = dacc[mt][nt];
            h2S[jb * APW + rA]       = fmaxf(fmaf(d[0], DOTSCALE, b0v), 0.f);
            h2S[(jb + 1) * APW + rA] = fmaxf(fmaf(d[1], DOTSCALE, b1v), 0.f);
            h2S[jb * APW + rB]       = fmaxf(fmaf(d[2], DOTSCALE, b0v), 0.f);
            h2S[(jb + 1) * APW + rB] = fmaxf(fmaf(d[3], DOTSCALE, b1v), 0.f);
        }
    }
    __syncthreads();

    {
        int r = tid & 63;
        int c = (tid >> 6) * 2;
        float a0 = 0.f, a1 = 0.f;
        #pragma unroll 4
        for (int d = 0; d < DIMC; d++) {
            float h = h2S[d * APW + r];
            a0 = fmaf(h, dw3[d * XD + c],     a0);
            a1 = fmaf(h, dw3[d * XD + c + 1], a1);
        }
        out_xt[(size_t)(rbase + r) * XD + c]     = a0 + db3[c];
        out_xt[(size_t)(rbase + r) * XD + c + 1] = a1 + db3[c + 1];
    }
}

// ---------------- launch ----------------
extern "C" void kernel_launch(void* const* d_in, const int* in_sizes, int n_in,
                              void* d_out, int out_size) {
    const float* state = (const float*)d_in[0];
    const float* x     = (const float*)d_in[1];
    const float* cb    = (const float*)d_in[2];
    const float* ew1   = (const float*)d_in[3];
    const float* eb1   = (const float*)d_in[4];
    const float* ew2   = (const float*)d_in[5];
    const float* eb2   = (const float*)d_in[6];
    const float* ew3   = (const float*)d_in[7];
    const float* eb3   = (const float*)d_in[8];
    const float* dw1   = (const float*)d_in[9];
    const float* db1   = (const float*)d_in[10];
    const float* dw2   = (const float*)d_in[11];
    const float* db2   = (const float*)d_in[12];
    const float* dw3   = (const float*)d_in[13];
    const float* db3   = (const float*)d_in[14];

    const int nrows = in_sizes[0] / SDIM;   // 262144

    static bool attrs_set = false;
    if (!attrs_set) {
        cudaFuncSetAttribute((const void*)fused_kernel, cudaFuncAttributeMaxDynamicSharedMemorySize, F_SMEM);
        cudaFuncSetAttribute((const void*)dec_kernel,   cudaFuncAttributeMaxDynamicSharedMemorySize, DEC_SMEM);
        attrs_set = true;
    }

    vq_prep<<<KC, DIMC>>>(cb);
    dec_prep<<<(128 * 384 + 128 * 128 + 255) / 256, 256>>>(dw1, dw2);
    fused_kernel<<<nrows / ROWS, NTHR, F_SMEM>>>(state, x, ew1, eb1, ew2, eb2, ew3, eb3,
                                                 cb, (float*)d_out, nrows);
    dec_kernel<<<nrows / DROWS, DTHR, DEC_SMEM>>>(state, cb, db1, db2, dw3, db3,
                                                  (float*)d_out, nrows);
}